// round 13
// baseline (speedup 1.0000x reference)
#include <cuda_runtime.h>
#include <cstdint>

#define BATCH 8
#define NTOK  4096
#define CIN   192
#define HID   768
#define EPSBN 1e-5f

#define XT_N (BATCH * NTOK * CIN)   // 6291456
#define W_N  (HID * CIN)            // 147456

// Scratch
__device__ float  g_ht[(size_t)BATCH * HID * NTOK];   // hidden, [B,H,N], ~100.7MB
__device__ float  g_xt[XT_N];                         // tf32-rounded x
__device__ float  g_w1t[W_N];                         // tf32-rounded W1
__device__ float  g_w2t[W_N];                         // tf32-rounded W2
__device__ float2 g_tw[NTOK];                         // forward twiddles

// padded smem index for FFT buffers
#define PAD(i) ((i) + ((i) >> 5))
#define FFT_BUF 4224

// ---------------------------------------------------------------------------
__device__ __forceinline__ float tf32r(float x)
{
    uint32_t r;
    asm("cvt.rna.tf32.f32 %0, %1;" : "=r"(r) : "f"(x));
    return __uint_as_float(r);
}

__device__ __forceinline__ void mma_tf32(float4& d, const uint32_t* a, const uint32_t* b)
{
    asm volatile(
        "mma.sync.aligned.m16n8k8.row.col.f32.tf32.tf32.f32 "
        "{%0,%1,%2,%3}, {%4,%5,%6,%7}, {%8,%9}, {%0,%1,%2,%3};"
        : "+f"(d.x), "+f"(d.y), "+f"(d.z), "+f"(d.w)
        : "r"(a[0]), "r"(a[1]), "r"(a[2]), "r"(a[3]), "r"(b[0]), "r"(b[1]));
}

__device__ __forceinline__ void cp_async16(uint32_t saddr, const void* gptr)
{
    asm volatile("cp.async.cg.shared.global [%0], [%1], 16;" :: "r"(saddr), "l"(gptr));
}
#define CP_COMMIT() asm volatile("cp.async.commit_group;")
#define CP_WAIT1()  asm volatile("cp.async.wait_group 1;")

// ---------------------------------------------------------------------------
__global__ void twiddle_init_k()
{
    int t = blockIdx.x * blockDim.x + threadIdx.x;
    if (t < NTOK) {
        float s, c;
        sincospif(-2.0f * (float)t / (float)NTOK, &s, &c);
        g_tw[t] = make_float2(c, s);
    }
}

// RN-round inputs to tf32 once (so GEMMs can feed raw bits losslessly)
__global__ void prep_k(const float* __restrict__ x, const float* __restrict__ W1,
                       const float* __restrict__ W2)
{
    int idx = blockIdx.x * blockDim.x + threadIdx.x;   // float4 index
    const float4* src;
    float4* dst;
    int off;
    if (idx < XT_N / 4)                 { src = (const float4*)x;  dst = (float4*)g_xt;  off = idx; }
    else if (idx < (XT_N + W_N) / 4)    { src = (const float4*)W1; dst = (float4*)g_w1t; off = idx - XT_N / 4; }
    else                                { src = (const float4*)W2; dst = (float4*)g_w2t; off = idx - (XT_N + W_N) / 4; }
    float4 v = src[off];
    v.x = tf32r(v.x); v.y = tf32r(v.y); v.z = tf32r(v.z); v.w = tf32r(v.w);
    dst[off] = v;
}

// ---------------------------------------------------------------------------
// GEMM1 (tf32, cp.async 3-stage): ht[b,h,n] = relu(BN( sum_c x[b,n,c]*W1[h,c] ))
// Per-batch launch: grid (32, 6), batch passed as arg.
// ---------------------------------------------------------------------------
#define G1_SSZ (128 * 20 * 2)
#define G1_SMEM (3 * G1_SSZ * 4)

__global__ __launch_bounds__(256) void gemm1_k(int b,
    const float* __restrict__ g1, const float* __restrict__ b1,
    const float* __restrict__ m1, const float* __restrict__ v1)
{
    extern __shared__ uint32_t smem_u[];

    int tid  = threadIdx.x;
    int lane = tid & 31;
    int wid  = tid >> 5;
    int wm   = wid & 1;
    int wn   = wid >> 1;
    int lk   = lane & 3;
    int lg   = lane >> 2;

    int n0 = blockIdx.x * 128;
    int h0 = blockIdx.y * 128;

    const float* wp = g_w1t + (size_t)h0 * CIN;
    const float* xp = g_xt + ((size_t)b * NTOK + n0) * CIN;

    uint32_t sbase = (uint32_t)__cvta_generic_to_shared(smem_u);

    int lrow = tid >> 2;
    int lko  = (tid & 3) << 2;

#define G1_LOAD(st, kc)                                                          \
    {                                                                            \
        uint32_t ao = sbase + (st) * G1_SSZ * 4;                                 \
        uint32_t bo = ao + 128 * 20 * 4;                                         \
        _Pragma("unroll")                                                        \
        for (int i = 0; i < 2; i++) {                                            \
            int row = lrow + i * 64;                                             \
            cp_async16(ao + (row * 20 + lko) * 4, wp + (size_t)row * CIN + (kc) * 16 + lko); \
            cp_async16(bo + (row * 20 + lko) * 4, xp + (size_t)row * CIN + (kc) * 16 + lko); \
        }                                                                        \
    }

    float4 acc[4][4];
#pragma unroll
    for (int i = 0; i < 4; i++)
#pragma unroll
        for (int j = 0; j < 4; j++) acc[i][j] = make_float4(0.f, 0.f, 0.f, 0.f);

    G1_LOAD(0, 0); CP_COMMIT();
    G1_LOAD(1, 1); CP_COMMIT();

    for (int kc = 0; kc < 12; kc++) {
        CP_WAIT1();
        __syncthreads();
        if (kc + 2 < 12) { G1_LOAD((kc + 2) % 3, kc + 2); }
        CP_COMMIT();

        const uint32_t* sA = smem_u + (kc % 3) * G1_SSZ;
        const uint32_t* sB = sA + 128 * 20;
#pragma unroll
        for (int k0 = 0; k0 < 16; k0 += 8) {
            uint32_t afr[4][4], bfr[4][2];
#pragma unroll
            for (int mf = 0; mf < 4; mf++) {
                int mb = wm * 64 + mf * 16 + lg;
                afr[mf][0] = sA[(mb    ) * 20 + k0 + lk    ];
                afr[mf][1] = sA[(mb + 8) * 20 + k0 + lk    ];
                afr[mf][2] = sA[(mb    ) * 20 + k0 + lk + 4];
                afr[mf][3] = sA[(mb + 8) * 20 + k0 + lk + 4];
            }
#pragma unroll
            for (int nf = 0; nf < 4; nf++) {
                int nb = wn * 32 + nf * 8 + lg;
                bfr[nf][0] = sB[nb * 20 + k0 + lk    ];
                bfr[nf][1] = sB[nb * 20 + k0 + lk + 4];
            }
#pragma unroll
            for (int mf = 0; mf < 4; mf++)
#pragma unroll
                for (int nf = 0; nf < 4; nf++)
                    mma_tf32(acc[mf][nf], afr[mf], bfr[nf]);
        }
    }

#pragma unroll
    for (int mf = 0; mf < 4; mf++) {
        int h_r0 = h0 + wm * 64 + mf * 16 + lg;
        int h_r1 = h_r0 + 8;
        float sc0 = g1[h_r0] * rsqrtf(v1[h_r0] + EPSBN);
        float sh0 = b1[h_r0] - m1[h_r0] * sc0;
        float sc1 = g1[h_r1] * rsqrtf(v1[h_r1] + EPSBN);
        float sh1 = b1[h_r1] - m1[h_r1] * sc1;
        float* p0 = g_ht + ((size_t)(b * HID + h_r0)) * NTOK + n0;
        float* p1 = g_ht + ((size_t)(b * HID + h_r1)) * NTOK + n0;
#pragma unroll
        for (int nf = 0; nf < 4; nf++) {
            int nc = wn * 32 + nf * 8 + 2 * lk;
            float4 a = acc[mf][nf];
            float2 o0, o1;
            o0.x = fmaxf(fmaf(a.x, sc0, sh0), 0.0f);
            o0.y = fmaxf(fmaf(a.y, sc0, sh0), 0.0f);
            o1.x = fmaxf(fmaf(a.z, sc1, sh1), 0.0f);
            o1.y = fmaxf(fmaf(a.w, sc1, sh1), 0.0f);
            *(float2*)(p0 + nc) = o0;
            *(float2*)(p1 + nc) = o1;
        }
    }
}

// ---------------------------------------------------------------------------
// Fused FFT -> pointwise -> IFFT. Radix-4 Stockham, 256 threads, gmem-fused
// end stages, single twiddle load per butterfly. Per-batch: grid = 384.
// ---------------------------------------------------------------------------
__device__ __forceinline__ float2 cmulf(float2 a, float2 b)
{
    return make_float2(fmaf(a.x, b.x, -a.y * b.y), fmaf(a.x, b.y, a.y * b.x));
}

template <bool INV>
__device__ __forceinline__ void r4bf(float2 a0, float2 a1, float2 a2, float2 a3,
                                     float2& X0, float2& X1, float2& X2, float2& X3)
{
    float2 t0 = make_float2(a0.x + a2.x, a0.y + a2.y);
    float2 t1 = make_float2(a0.x - a2.x, a0.y - a2.y);
    float2 t2 = make_float2(a1.x + a3.x, a1.y + a3.y);
    float2 u  = make_float2(a1.x - a3.x, a1.y - a3.y);
    float2 t3 = INV ? make_float2(-u.y, u.x) : make_float2(u.y, -u.x);
    X0 = make_float2(t0.x + t2.x, t0.y + t2.y);
    X1 = make_float2(t1.x + t3.x, t1.y + t3.y);
    X2 = make_float2(t0.x - t2.x, t0.y - t2.y);
    X3 = make_float2(t1.x - t3.x, t1.y - t3.y);
}

template <bool INV, int NS>
__device__ __forceinline__ void fft_stage(const float2* __restrict__ src,
                                          float2* __restrict__ dst)
{
    constexpr int STEP = (NTOK / 4) / NS;
#pragma unroll
    for (int q = 0; q < 4; q++) {
        int j = threadIdx.x + q * 256;
        int k = j & (NS - 1);
        float2 a0 = src[PAD(j)];
        float2 a1 = src[PAD(j + 1024)];
        float2 a2 = src[PAD(j + 2048)];
        float2 a3 = src[PAD(j + 3072)];
        if (NS > 1) {
            float2 w1 = g_tw[k * STEP];
            if (INV) w1.y = -w1.y;
            float2 w2 = cmulf(w1, w1);
            float2 w3 = cmulf(w1, w2);
            a1 = cmulf(w1, a1);
            a2 = cmulf(w2, a2);
            a3 = cmulf(w3, a3);
        }
        float2 X0, X1, X2, X3;
        r4bf<INV>(a0, a1, a2, a3, X0, X1, X2, X3);
        int base = ((j - k) << 2) + k;
        dst[PAD(base         )] = X0;
        dst[PAD(base +     NS)] = X1;
        dst[PAD(base + 2 * NS)] = X2;
        dst[PAD(base + 3 * NS)] = X3;
    }
    __syncthreads();
}

// forward stage 1 (NS=1, no twiddles) reading directly from the two real rows
__device__ __forceinline__ void fft_stage1_g(const float* __restrict__ row0,
                                             const float* __restrict__ row1,
                                             float2* __restrict__ dst)
{
#pragma unroll
    for (int q = 0; q < 4; q++) {
        int j = threadIdx.x + q * 256;
        float2 a0 = make_float2(row0[j       ], row1[j       ]);
        float2 a1 = make_float2(row0[j + 1024], row1[j + 1024]);
        float2 a2 = make_float2(row0[j + 2048], row1[j + 2048]);
        float2 a3 = make_float2(row0[j + 3072], row1[j + 3072]);
        float2 X0, X1, X2, X3;
        r4bf<false>(a0, a1, a2, a3, X0, X1, X2, X3);
        int base = j << 2;
        dst[PAD(base    )] = X0;
        dst[PAD(base + 1)] = X1;
        dst[PAD(base + 2)] = X2;
        dst[PAD(base + 3)] = X3;
    }
    __syncthreads();
}

// inverse stage 6 (NS=1024): outputs are coalesced -> write gmem directly
__device__ __forceinline__ void fft_stage6_inv_g(const float2* __restrict__ src,
                                                 float* __restrict__ row0,
                                                 float* __restrict__ row1)
{
    const float inv = 0.015625f;        // 1/sqrt(4096)
#pragma unroll
    for (int q = 0; q < 4; q++) {
        int j = threadIdx.x + q * 256;  // 0..1023 ; k = j, base = j
        float2 a0 = src[PAD(j)];
        float2 a1 = src[PAD(j + 1024)];
        float2 a2 = src[PAD(j + 2048)];
        float2 a3 = src[PAD(j + 3072)];
        float2 w1 = g_tw[j];
        w1.y = -w1.y;                   // inverse
        float2 w2 = cmulf(w1, w1);
        float2 w3 = cmulf(w1, w2);
        a1 = cmulf(w1, a1);
        a2 = cmulf(w2, a2);
        a3 = cmulf(w3, a3);
        float2 X0, X1, X2, X3;
        r4bf<true>(a0, a1, a2, a3, X0, X1, X2, X3);
        row0[j       ] = tf32r(X0.x * inv);
        row1[j       ] = tf32r(X0.y * inv);
        row0[j + 1024] = tf32r(X1.x * inv);
        row1[j + 1024] = tf32r(X1.y * inv);
        row0[j + 2048] = tf32r(X2.x * inv);
        row1[j + 2048] = tf32r(X2.y * inv);
        row0[j + 3072] = tf32r(X3.x * inv);
        row1[j + 3072] = tf32r(X3.y * inv);
    }
}

__device__ __forceinline__ float2 pointwise(float2 X, float ra, float ia,
                                            float rbv, float ibv)
{
    float xr = fmaxf(fmaf(ra, X.x, fmaf(-ia, X.y, rbv)), 0.0f);
    float xi = fmaxf(fmaf(ra, X.y, fmaf(ia, X.x, ibv)), 0.0f);
    return make_float2(xr, xi);
}

__global__ __launch_bounds__(256) void fftmix_k(int b,
    const float* __restrict__ rmat, const float* __restrict__ imat,
    const float* __restrict__ rb,   const float* __restrict__ ib)
{
    extern __shared__ float2 sb[];
    float2* b0 = sb;
    float2* b1 = sb + FFT_BUF;

    int hp  = blockIdx.x;               // 0..383
    int h0  = 2 * hp;
    int h1  = h0 + 1;
    float* row0 = g_ht + ((size_t)(b * HID + h0)) * NTOK;
    float* row1 = row0 + NTOK;
    int tid = threadIdx.x;

    // forward FFT: gmem -> b0, then 5 smem stages; Z ends in b1
    fft_stage1_g(row0, row1, b0);
    fft_stage<false, 4>(b0, b1);
    fft_stage<false, 16>(b1, b0);
    fft_stage<false, 64>(b0, b1);
    fft_stage<false, 256>(b1, b0);
    fft_stage<false, 1024>(b0, b1);

    float ra0 = rmat[(size_t)h0 * HID + h0];
    float ia0 = imat[(size_t)h0 * HID + h0];
    float ra1 = rmat[(size_t)h1 * HID + h1];
    float ia1 = imat[(size_t)h1 * HID + h1];
    float rb0 = rb[h0], ib0 = ib[h0];
    float rb1 = rb[h1], ib1 = ib[h1];
    const float inv = 0.015625f;        // 1/sqrt(4096)

    // unpack -> pointwise -> Hermitian-project -> repack on b1, pairs (k, N-k)
    for (int p = tid; p < 2048; p += 256) {
        int k = p;
        int m = (NTOK - p) & (NTOK - 1);
#pragma unroll
        for (int rep = 0; rep < 2; rep++) {
            if (rep == 1) {
                if (p != 0) break;
                k = 2048; m = 2048;
            }
            float2 Zk = b1[PAD(k)];
            float2 Zm = b1[PAD(m)];
            float hv = 0.5f * inv;
            float2 X0k = make_float2((Zk.x + Zm.x) * hv, (Zk.y - Zm.y) * hv);
            float2 X1k = make_float2((Zk.y + Zm.y) * hv, (Zm.x - Zk.x) * hv);
            float2 X0m = make_float2((Zm.x + Zk.x) * hv, (Zm.y - Zk.y) * hv);
            float2 X1m = make_float2((Zm.y + Zk.y) * hv, (Zk.x - Zm.x) * hv);

            float2 S0k = pointwise(X0k, ra0, ia0, rb0, ib0);
            float2 S0m = pointwise(X0m, ra0, ia0, rb0, ib0);
            float2 S1k = pointwise(X1k, ra1, ia1, rb1, ib1);
            float2 S1m = pointwise(X1m, ra1, ia1, rb1, ib1);

            float2 H0 = make_float2(0.5f * (S0k.x + S0m.x), 0.5f * (S0k.y - S0m.y));
            float2 H1 = make_float2(0.5f * (S1k.x + S1m.x), 0.5f * (S1k.y - S1m.y));
            b1[PAD(k)] = make_float2(H0.x - H1.y, H0.y + H1.x);
            if (m != k)
                b1[PAD(m)] = make_float2(H0.x + H1.y, H1.x - H0.y);
        }
    }
    __syncthreads();

    // inverse FFT: 5 smem stages, final stage writes gmem (scaled, tf32-rounded)
    fft_stage<true, 1>(b1, b0);
    fft_stage<true, 4>(b0, b1);
    fft_stage<true, 16>(b1, b0);
    fft_stage<true, 64>(b0, b1);
    fft_stage<true, 256>(b1, b0);
    fft_stage6_inv_g(b0, row0, row1);
}

// ---------------------------------------------------------------------------
// GEMM2 (tf32, cp.async 3-stage): y[b,n,c] = BN( sum_h ht[b,h,n] * W2[c,h] )
// Per-batch launch: grid (16, 3).
// ---------------------------------------------------------------------------
#define G2_ASZ (16 * 264)
#define G2_WSZ (64 * 20)
#define G2_SSZ (G2_ASZ + G2_WSZ)
#define G2_SMEM (3 * G2_SSZ * 4)

__global__ __launch_bounds__(256) void gemm2_k(int b,
    const float* __restrict__ g2, const float* __restrict__ b2,
    const float* __restrict__ m2, const float* __restrict__ v2,
    float* __restrict__ y)
{
    extern __shared__ uint32_t smem_u[];

    int tid  = threadIdx.x;
    int lane = tid & 31;
    int wid  = tid >> 5;
    int wm   = wid >> 1;
    int wn   = wid & 1;
    int lk   = lane & 3;
    int lg   = lane >> 2;

    int n0 = blockIdx.x * 256;
    int c0 = blockIdx.y * 64;

    const float* hp = g_ht + (size_t)b * HID * NTOK + n0;
    const float* wp = g_w2t + (size_t)c0 * HID;

    uint32_t sbase = (uint32_t)__cvta_generic_to_shared(smem_u);

    int arow = tid >> 6;
    int aoff = (tid & 63) << 2;
    int wrow = tid >> 2;
    int woff = (tid & 3) << 2;

#define G2_LOAD(st, kc)                                                          \
    {                                                                            \
        uint32_t ao = sbase + (st) * G2_SSZ * 4;                                 \
        uint32_t wo = ao + G2_ASZ * 4;                                           \
        _Pragma("unroll")                                                        \
        for (int i = 0; i < 4; i++) {                                            \
            int row = arow + i * 4;                                              \
            cp_async16(ao + (row * 264 + aoff) * 4,                              \
                       hp + (size_t)((kc) * 16 + row) * NTOK + aoff);            \
        }                                                                        \
        cp_async16(wo + (wrow * 20 + woff) * 4,                                  \
                   wp + (size_t)wrow * HID + (kc) * 16 + woff);                  \
    }

    float4 acc[4][4];
#pragma unroll
    for (int i = 0; i < 4; i++)
#pragma unroll
        for (int j = 0; j < 4; j++) acc[i][j] = make_float4(0.f, 0.f, 0.f, 0.f);

    G2_LOAD(0, 0); CP_COMMIT();
    G2_LOAD(1, 1); CP_COMMIT();

    for (int kc = 0; kc < 48; kc++) {
        CP_WAIT1();
        __syncthreads();
        if (kc + 2 < 48) { G2_LOAD((kc + 2) % 3, kc + 2); }
        CP_COMMIT();

        const uint32_t* sA = smem_u + (kc % 3) * G2_SSZ;
        const uint32_t* sW = sA + G2_ASZ;
#pragma unroll
        for (int k0 = 0; k0 < 16; k0 += 8) {
            uint32_t afr[4][4], bfr[4][2];
#pragma unroll
            for (int mf = 0; mf < 4; mf++) {
                int mb = wm * 64 + mf * 16 + lg;
                afr[mf][0] = sA[(k0 + lk    ) * 264 + mb    ];
                afr[mf][1] = sA[(k0 + lk    ) * 264 + mb + 8];
                afr[mf][2] = sA[(k0 + lk + 4) * 264 + mb    ];
                afr[mf][3] = sA[(k0 + lk + 4) * 264 + mb + 8];
            }
#pragma unroll
            for (int nf = 0; nf < 4; nf++) {
                int cb = wn * 32 + nf * 8 + lg;
                bfr[nf][0] = sW[cb * 20 + k0 + lk    ];
                bfr[nf][1] = sW[cb * 20 + k0 + lk + 4];
            }
#pragma unroll
            for (int mf = 0; mf < 4; mf++)
#pragma unroll
                for (int nf = 0; nf < 4; nf++)
                    mma_tf32(acc[mf][nf], afr[mf], bfr[nf]);
        }
    }

    float scv[4][2], shv[4][2];
#pragma unroll
    for (int nf = 0; nf < 4; nf++) {
        int c = c0 + wn * 32 + nf * 8 + 2 * lk;
#pragma unroll
        for (int j = 0; j < 2; j++) {
            scv[nf][j] = g2[c + j] * rsqrtf(v2[c + j] + EPSBN);
            shv[nf][j] = b2[c + j] - m2[c + j] * scv[nf][j];
        }
    }
#pragma unroll
    for (int mf = 0; mf < 4; mf++) {
        int n_r0 = n0 + wm * 64 + mf * 16 + lg;
        int n_r1 = n_r0 + 8;
        float* p0 = y + ((size_t)(b * NTOK + n_r0)) * CIN;
        float* p1 = y + ((size_t)(b * NTOK + n_r1)) * CIN;
#pragma unroll
        for (int nf = 0; nf < 4; nf++) {
            int c = c0 + wn * 32 + nf * 8 + 2 * lk;
            float4 a = acc[mf][nf];
            float2 o0, o1;
            o0.x = fmaf(a.x, scv[nf][0], shv[nf][0]);
            o0.y = fmaf(a.y, scv[nf][1], shv[nf][1]);
            o1.x = fmaf(a.z, scv[nf][0], shv[nf][0]);
            o1.y = fmaf(a.w, scv[nf][1], shv[nf][1]);
            *(float2*)(p0 + c) = o0;
            *(float2*)(p1 + c) = o1;
        }
    }
}

// ---------------------------------------------------------------------------
// Launch: per-batch pipeline across 3 non-blocking streams, chained by events.
// gemm1(b) -> fftmix(b) -> gemm2(b); different batches overlap.
// ---------------------------------------------------------------------------
extern "C" void kernel_launch(void* const* d_in, const int* in_sizes, int n_in,
                              void* d_out, int out_size)
{
    const float* x  = (const float*)d_in[0];
    const float* W1 = (const float*)d_in[1];
    const float* g1 = (const float*)d_in[2];
    const float* b1 = (const float*)d_in[3];
    const float* m1 = (const float*)d_in[4];
    const float* v1 = (const float*)d_in[5];
    const float* r  = (const float*)d_in[6];
    const float* im = (const float*)d_in[7];
    const float* rb = (const float*)d_in[8];
    const float* ib = (const float*)d_in[9];
    const float* W2 = (const float*)d_in[10];
    const float* g2 = (const float*)d_in[11];
    const float* b2 = (const float*)d_in[12];
    const float* m2 = (const float*)d_in[13];
    const float* v2 = (const float*)d_in[14];
    float* y = (float*)d_out;

    static bool init_done = false;
    static cudaStream_t s1, s2, s3;
    static cudaEvent_t eP, e1[BATCH], e2[BATCH], eJ;
    if (!init_done) {
        cudaFuncSetAttribute(fftmix_k, cudaFuncAttributeMaxDynamicSharedMemorySize,
                             2 * FFT_BUF * sizeof(float2));
        cudaFuncSetAttribute(gemm1_k, cudaFuncAttributeMaxDynamicSharedMemorySize, G1_SMEM);
        cudaFuncSetAttribute(gemm2_k, cudaFuncAttributeMaxDynamicSharedMemorySize, G2_SMEM);
        cudaStreamCreateWithFlags(&s1, cudaStreamNonBlocking);
        cudaStreamCreateWithFlags(&s2, cudaStreamNonBlocking);
        cudaStreamCreateWithFlags(&s3, cudaStreamNonBlocking);
        cudaEventCreateWithFlags(&eP, cudaEventDisableTiming);
        for (int b = 0; b < BATCH; b++) {
            cudaEventCreateWithFlags(&e1[b], cudaEventDisableTiming);
            cudaEventCreateWithFlags(&e2[b], cudaEventDisableTiming);
        }
        cudaEventCreateWithFlags(&eJ, cudaEventDisableTiming);
        init_done = true;
    }

    // prologue on the launch stream
    prep_k<<<(XT_N + 2 * W_N) / 4 / 256, 256>>>(x, W1, W2);
    twiddle_init_k<<<16, 256>>>();
    cudaEventRecord(eP, 0);

    // fork
    cudaStreamWaitEvent(s1, eP, 0);
    cudaStreamWaitEvent(s2, eP, 0);

    for (int b = 0; b < BATCH; b++) {
        gemm1_k<<<dim3(NTOK / 128, HID / 128), 256, G1_SMEM, s1>>>(b, g1, b1, m1, v1);
        cudaEventRecord(e1[b], s1);
    }
    for (int b = 0; b < BATCH; b++) {
        cudaStreamWaitEvent(s2, e1[b], 0);
        fftmix_k<<<HID / 2, 256, 2 * FFT_BUF * sizeof(float2), s2>>>(b, r, im, rb, ib);
        cudaEventRecord(e2[b], s2);
    }
    for (int b = 0; b < BATCH; b++) {
        cudaStreamWaitEvent(s3, e2[b], 0);
        gemm2_k<<<dim3(NTOK / 256, CIN / 64), 256, G2_SMEM, s3>>>(b, g2, b2, m2, v2, y);
    }

    // join back to the launch stream
    cudaEventRecord(eJ, s3);
    cudaStreamWaitEvent(0, eJ, 0);
}

// round 15
// speedup vs baseline: 1.3293x; 1.3293x over previous
#include <cuda_runtime.h>
#include <cstdint>

#define BATCH 8
#define NTOK  4096
#define CIN   192
#define HID   768
#define EPSBN 1e-5f

#define XT_N (BATCH * NTOK * CIN)   // 6291456
#define W_N  (HID * CIN)            // 147456

// Scratch
__device__ float  g_ht[(size_t)BATCH * HID * NTOK];   // hidden, [B,H,N], ~100.7MB
__device__ float  g_xt[XT_N];                         // tf32-rounded x
__device__ float  g_w1t[W_N];                         // tf32-rounded W1
__device__ float  g_w2t[W_N];                         // tf32-rounded W2
__device__ float2 g_tw[NTOK];                         // forward twiddles

// padded smem index for FFT buffers
#define PAD(i) ((i) + ((i) >> 5))
#define FFT_BUF 4224

// ---------------------------------------------------------------------------
__device__ __forceinline__ float tf32r(float x)
{
    uint32_t r;
    asm("cvt.rna.tf32.f32 %0, %1;" : "=r"(r) : "f"(x));
    return __uint_as_float(r);
}

__device__ __forceinline__ void mma_tf32(float4& d, const uint32_t* a, const uint32_t* b)
{
    asm volatile(
        "mma.sync.aligned.m16n8k8.row.col.f32.tf32.tf32.f32 "
        "{%0,%1,%2,%3}, {%4,%5,%6,%7}, {%8,%9}, {%0,%1,%2,%3};"
        : "+f"(d.x), "+f"(d.y), "+f"(d.z), "+f"(d.w)
        : "r"(a[0]), "r"(a[1]), "r"(a[2]), "r"(a[3]), "r"(b[0]), "r"(b[1]));
}

__device__ __forceinline__ void cp_async16(uint32_t saddr, const void* gptr)
{
    asm volatile("cp.async.cg.shared.global [%0], [%1], 16;" :: "r"(saddr), "l"(gptr));
}
#define CP_COMMIT() asm volatile("cp.async.commit_group;")
#define CP_WAIT1()  asm volatile("cp.async.wait_group 1;")

// ---------------------------------------------------------------------------
__global__ void twiddle_init_k()
{
    int t = blockIdx.x * blockDim.x + threadIdx.x;
    if (t < NTOK) {
        float s, c;
        sincospif(-2.0f * (float)t / (float)NTOK, &s, &c);
        g_tw[t] = make_float2(c, s);
    }
}

// RN-round inputs to tf32 once (so GEMMs can feed raw bits losslessly)
__global__ void prep_k(const float* __restrict__ x, const float* __restrict__ W1,
                       const float* __restrict__ W2)
{
    int idx = blockIdx.x * blockDim.x + threadIdx.x;   // float4 index
    const float4* src;
    float4* dst;
    int off;
    if (idx < XT_N / 4)                 { src = (const float4*)x;  dst = (float4*)g_xt;  off = idx; }
    else if (idx < (XT_N + W_N) / 4)    { src = (const float4*)W1; dst = (float4*)g_w1t; off = idx - XT_N / 4; }
    else                                { src = (const float4*)W2; dst = (float4*)g_w2t; off = idx - (XT_N + W_N) / 4; }
    float4 v = src[off];
    v.x = tf32r(v.x); v.y = tf32r(v.y); v.z = tf32r(v.z); v.w = tf32r(v.w);
    dst[off] = v;
}

// ---------------------------------------------------------------------------
// GEMM1 (tf32, cp.async 3-stage): ht[b,h,n] = relu(BN( sum_c x[b,n,c]*W1[h,c] ))
// ---------------------------------------------------------------------------
#define G1_SSZ (128 * 20 * 2)
#define G1_SMEM (3 * G1_SSZ * 4)

__global__ __launch_bounds__(256) void gemm1_k(
    const float* __restrict__ g1, const float* __restrict__ b1,
    const float* __restrict__ m1, const float* __restrict__ v1)
{
    extern __shared__ uint32_t smem_u[];

    int tid  = threadIdx.x;
    int lane = tid & 31;
    int wid  = tid >> 5;
    int wm   = wid & 1;
    int wn   = wid >> 1;
    int lk   = lane & 3;
    int lg   = lane >> 2;

    int n0 = blockIdx.x * 128;
    int h0 = blockIdx.y * 128;
    int b  = blockIdx.z;

    const float* wp = g_w1t + (size_t)h0 * CIN;
    const float* xp = g_xt + ((size_t)b * NTOK + n0) * CIN;

    uint32_t sbase = (uint32_t)__cvta_generic_to_shared(smem_u);

    int lrow = tid >> 2;
    int lko  = (tid & 3) << 2;

#define G1_LOAD(st, kc)                                                          \
    {                                                                            \
        uint32_t ao = sbase + (st) * G1_SSZ * 4;                                 \
        uint32_t bo = ao + 128 * 20 * 4;                                         \
        _Pragma("unroll")                                                        \
        for (int i = 0; i < 2; i++) {                                            \
            int row = lrow + i * 64;                                             \
            cp_async16(ao + (row * 20 + lko) * 4, wp + (size_t)row * CIN + (kc) * 16 + lko); \
            cp_async16(bo + (row * 20 + lko) * 4, xp + (size_t)row * CIN + (kc) * 16 + lko); \
        }                                                                        \
    }

    float4 acc[4][4];
#pragma unroll
    for (int i = 0; i < 4; i++)
#pragma unroll
        for (int j = 0; j < 4; j++) acc[i][j] = make_float4(0.f, 0.f, 0.f, 0.f);

    G1_LOAD(0, 0); CP_COMMIT();
    G1_LOAD(1, 1); CP_COMMIT();

    for (int kc = 0; kc < 12; kc++) {
        CP_WAIT1();
        __syncthreads();
        if (kc + 2 < 12) { G1_LOAD((kc + 2) % 3, kc + 2); }
        CP_COMMIT();

        const uint32_t* sA = smem_u + (kc % 3) * G1_SSZ;
        const uint32_t* sB = sA + 128 * 20;
#pragma unroll
        for (int k0 = 0; k0 < 16; k0 += 8) {
            uint32_t afr[4][4], bfr[4][2];
#pragma unroll
            for (int mf = 0; mf < 4; mf++) {
                int mb = wm * 64 + mf * 16 + lg;
                afr[mf][0] = sA[(mb    ) * 20 + k0 + lk    ];
                afr[mf][1] = sA[(mb + 8) * 20 + k0 + lk    ];
                afr[mf][2] = sA[(mb    ) * 20 + k0 + lk + 4];
                afr[mf][3] = sA[(mb + 8) * 20 + k0 + lk + 4];
            }
#pragma unroll
            for (int nf = 0; nf < 4; nf++) {
                int nb = wn * 32 + nf * 8 + lg;
                bfr[nf][0] = sB[nb * 20 + k0 + lk    ];
                bfr[nf][1] = sB[nb * 20 + k0 + lk + 4];
            }
#pragma unroll
            for (int mf = 0; mf < 4; mf++)
#pragma unroll
                for (int nf = 0; nf < 4; nf++)
                    mma_tf32(acc[mf][nf], afr[mf], bfr[nf]);
        }
    }

#pragma unroll
    for (int mf = 0; mf < 4; mf++) {
        int h_r0 = h0 + wm * 64 + mf * 16 + lg;
        int h_r1 = h_r0 + 8;
        float sc0 = g1[h_r0] * rsqrtf(v1[h_r0] + EPSBN);
        float sh0 = b1[h_r0] - m1[h_r0] * sc0;
        float sc1 = g1[h_r1] * rsqrtf(v1[h_r1] + EPSBN);
        float sh1 = b1[h_r1] - m1[h_r1] * sc1;
        float* p0 = g_ht + ((size_t)(b * HID + h_r0)) * NTOK + n0;
        float* p1 = g_ht + ((size_t)(b * HID + h_r1)) * NTOK + n0;
#pragma unroll
        for (int nf = 0; nf < 4; nf++) {
            int nc = wn * 32 + nf * 8 + 2 * lk;
            float4 a = acc[mf][nf];
            float2 o0, o1;
            o0.x = fmaxf(fmaf(a.x, sc0, sh0), 0.0f);
            o0.y = fmaxf(fmaf(a.y, sc0, sh0), 0.0f);
            o1.x = fmaxf(fmaf(a.z, sc1, sh1), 0.0f);
            o1.y = fmaxf(fmaf(a.w, sc1, sh1), 0.0f);
            *(float2*)(p0 + nc) = o0;
            *(float2*)(p1 + nc) = o1;
        }
    }
}

// ---------------------------------------------------------------------------
// Fused FFT -> pointwise -> IFFT. Radix-4 Stockham, 256 threads, gmem-fused
// end stages, single twiddle load per butterfly. Pointwise (unpack -> complex
// scale+bias+ReLU -> Hermitian repack) is fused into inverse stage 1's read.
// ---------------------------------------------------------------------------
__device__ __forceinline__ float2 cmulf(float2 a, float2 b)
{
    return make_float2(fmaf(a.x, b.x, -a.y * b.y), fmaf(a.x, b.y, a.y * b.x));
}

template <bool INV>
__device__ __forceinline__ void r4bf(float2 a0, float2 a1, float2 a2, float2 a3,
                                     float2& X0, float2& X1, float2& X2, float2& X3)
{
    float2 t0 = make_float2(a0.x + a2.x, a0.y + a2.y);
    float2 t1 = make_float2(a0.x - a2.x, a0.y - a2.y);
    float2 t2 = make_float2(a1.x + a3.x, a1.y + a3.y);
    float2 u  = make_float2(a1.x - a3.x, a1.y - a3.y);
    float2 t3 = INV ? make_float2(-u.y, u.x) : make_float2(u.y, -u.x);
    X0 = make_float2(t0.x + t2.x, t0.y + t2.y);
    X1 = make_float2(t1.x + t3.x, t1.y + t3.y);
    X2 = make_float2(t0.x - t2.x, t0.y - t2.y);
    X3 = make_float2(t1.x - t3.x, t1.y - t3.y);
}

template <bool INV, int NS>
__device__ __forceinline__ void fft_stage(const float2* __restrict__ src,
                                          float2* __restrict__ dst)
{
    constexpr int STEP = (NTOK / 4) / NS;
#pragma unroll
    for (int q = 0; q < 4; q++) {
        int j = threadIdx.x + q * 256;
        int k = j & (NS - 1);
        float2 a0 = src[PAD(j)];
        float2 a1 = src[PAD(j + 1024)];
        float2 a2 = src[PAD(j + 2048)];
        float2 a3 = src[PAD(j + 3072)];
        if (NS > 1) {
            float2 w1 = g_tw[k * STEP];
            if (INV) w1.y = -w1.y;
            float2 w2 = cmulf(w1, w1);
            float2 w3 = cmulf(w1, w2);
            a1 = cmulf(w1, a1);
            a2 = cmulf(w2, a2);
            a3 = cmulf(w3, a3);
        }
        float2 X0, X1, X2, X3;
        r4bf<INV>(a0, a1, a2, a3, X0, X1, X2, X3);
        int base = ((j - k) << 2) + k;
        dst[PAD(base         )] = X0;
        dst[PAD(base +     NS)] = X1;
        dst[PAD(base + 2 * NS)] = X2;
        dst[PAD(base + 3 * NS)] = X3;
    }
    __syncthreads();
}

// forward stage 1 (NS=1, no twiddles) reading directly from the two real rows
__device__ __forceinline__ void fft_stage1_g(const float* __restrict__ row0,
                                             const float* __restrict__ row1,
                                             float2* __restrict__ dst)
{
#pragma unroll
    for (int q = 0; q < 4; q++) {
        int j = threadIdx.x + q * 256;
        float2 a0 = make_float2(row0[j       ], row1[j       ]);
        float2 a1 = make_float2(row0[j + 1024], row1[j + 1024]);
        float2 a2 = make_float2(row0[j + 2048], row1[j + 2048]);
        float2 a3 = make_float2(row0[j + 3072], row1[j + 3072]);
        float2 X0, X1, X2, X3;
        r4bf<false>(a0, a1, a2, a3, X0, X1, X2, X3);
        int base = j << 2;
        dst[PAD(base    )] = X0;
        dst[PAD(base + 1)] = X1;
        dst[PAD(base + 2)] = X2;
        dst[PAD(base + 3)] = X3;
    }
    __syncthreads();
}

// pointwise for one packed-pair spectrum element:
// given Zk = Z[P] and Zm = Z[(N-P) mod N], returns T[P] (repacked, scaled)
struct PwParams {
    float ra0, ia0, ra1, ia1, rb0, ib0, rb1, ib1;
};

__device__ __forceinline__ float2 pw_elem(float2 Zk, float2 Zm, const PwParams& P)
{
    const float hv = 0.5f * 0.015625f;   // 0.5 / sqrt(4096)
    float2 X0k = make_float2((Zk.x + Zm.x) * hv, (Zk.y - Zm.y) * hv);
    float2 X1k = make_float2((Zk.y + Zm.y) * hv, (Zm.x - Zk.x) * hv);
    float2 X0m = make_float2((Zm.x + Zk.x) * hv, (Zm.y - Zk.y) * hv);
    float2 X1m = make_float2((Zm.y + Zk.y) * hv, (Zk.x - Zm.x) * hv);

    float2 S0k, S0m, S1k, S1m;
    S0k.x = fmaxf(fmaf(P.ra0, X0k.x, fmaf(-P.ia0, X0k.y, P.rb0)), 0.0f);
    S0k.y = fmaxf(fmaf(P.ra0, X0k.y, fmaf( P.ia0, X0k.x, P.ib0)), 0.0f);
    S0m.x = fmaxf(fmaf(P.ra0, X0m.x, fmaf(-P.ia0, X0m.y, P.rb0)), 0.0f);
    S0m.y = fmaxf(fmaf(P.ra0, X0m.y, fmaf( P.ia0, X0m.x, P.ib0)), 0.0f);
    S1k.x = fmaxf(fmaf(P.ra1, X1k.x, fmaf(-P.ia1, X1k.y, P.rb1)), 0.0f);
    S1k.y = fmaxf(fmaf(P.ra1, X1k.y, fmaf( P.ia1, X1k.x, P.ib1)), 0.0f);
    S1m.x = fmaxf(fmaf(P.ra1, X1m.x, fmaf(-P.ia1, X1m.y, P.rb1)), 0.0f);
    S1m.y = fmaxf(fmaf(P.ra1, X1m.y, fmaf( P.ia1, X1m.x, P.ib1)), 0.0f);

    // Hermitian projection: H[k] = (S[k] + conj(S[m])) / 2 ; T = H0 + i*H1
    float2 H0 = make_float2(0.5f * (S0k.x + S0m.x), 0.5f * (S0k.y - S0m.y));
    float2 H1 = make_float2(0.5f * (S1k.x + S1m.x), 0.5f * (S1k.y - S1m.y));
    return make_float2(H0.x - H1.y, H0.y + H1.x);
}

// inverse stage 1 (NS=1) with the pointwise fused into the read.
// thread element positions {j, j+1024, j+2048, j+3072}; Hermitian partners
// are {(4096-j)&4095, 3072-j, 2048-j, 1024-j} (self-pairs handled by formula).
__device__ __forceinline__ void inv_stage1_pw(const float2* __restrict__ src,
                                              float2* __restrict__ dst,
                                              const PwParams& P)
{
#pragma unroll
    for (int q = 0; q < 4; q++) {
        int j = threadIdx.x + q * 256;      // 0..1023
        float2 Z0 = src[PAD(j)];
        float2 Z1 = src[PAD(j + 1024)];
        float2 Z2 = src[PAD(j + 2048)];
        float2 Z3 = src[PAD(j + 3072)];
        int m0 = (NTOK - j) & (NTOK - 1);
        float2 M0 = src[PAD(m0)];
        float2 M1 = src[PAD(3072 - j)];
        float2 M2 = src[PAD(2048 - j)];
        float2 M3 = src[PAD(1024 - j)];

        float2 a0 = pw_elem(Z0, M0, P);
        float2 a1 = pw_elem(Z1, M1, P);
        float2 a2 = pw_elem(Z2, M2, P);
        float2 a3 = pw_elem(Z3, M3, P);

        float2 X0, X1, X2, X3;
        r4bf<true>(a0, a1, a2, a3, X0, X1, X2, X3);
        int base = j << 2;
        dst[PAD(base    )] = X0;
        dst[PAD(base + 1)] = X1;
        dst[PAD(base + 2)] = X2;
        dst[PAD(base + 3)] = X3;
    }
    __syncthreads();
}

// inverse stage 6 (NS=1024): outputs are coalesced -> write gmem directly
__device__ __forceinline__ void fft_stage6_inv_g(const float2* __restrict__ src,
                                                 float* __restrict__ row0,
                                                 float* __restrict__ row1)
{
    const float inv = 0.015625f;        // 1/sqrt(4096)
#pragma unroll
    for (int q = 0; q < 4; q++) {
        int j = threadIdx.x + q * 256;  // 0..1023 ; k = j, base = j
        float2 a0 = src[PAD(j)];
        float2 a1 = src[PAD(j + 1024)];
        float2 a2 = src[PAD(j + 2048)];
        float2 a3 = src[PAD(j + 3072)];
        float2 w1 = g_tw[j];
        w1.y = -w1.y;                   // inverse
        float2 w2 = cmulf(w1, w1);
        float2 w3 = cmulf(w1, w2);
        a1 = cmulf(w1, a1);
        a2 = cmulf(w2, a2);
        a3 = cmulf(w3, a3);
        float2 X0, X1, X2, X3;
        r4bf<true>(a0, a1, a2, a3, X0, X1, X2, X3);
        row0[j       ] = tf32r(X0.x * inv);
        row1[j       ] = tf32r(X0.y * inv);
        row0[j + 1024] = tf32r(X1.x * inv);
        row1[j + 1024] = tf32r(X1.y * inv);
        row0[j + 2048] = tf32r(X2.x * inv);
        row1[j + 2048] = tf32r(X2.y * inv);
        row0[j + 3072] = tf32r(X3.x * inv);
        row1[j + 3072] = tf32r(X3.y * inv);
    }
}

__global__ __launch_bounds__(256) void fftmix_k(
    const float* __restrict__ rmat, const float* __restrict__ imat,
    const float* __restrict__ rb,   const float* __restrict__ ib)
{
    extern __shared__ float2 sb[];
    float2* b0 = sb;
    float2* b1 = sb + FFT_BUF;

    int blk = blockIdx.x;
    int b   = blk / (HID / 2);
    int hp  = blk % (HID / 2);
    int h0  = 2 * hp;
    int h1  = h0 + 1;
    float* row0 = g_ht + ((size_t)(b * HID + h0)) * NTOK;
    float* row1 = row0 + NTOK;

    // forward FFT: gmem -> b0, then 5 smem stages; Z ends in b1
    fft_stage1_g(row0, row1, b0);
    fft_stage<false, 4>(b0, b1);
    fft_stage<false, 16>(b1, b0);
    fft_stage<false, 64>(b0, b1);
    fft_stage<false, 256>(b1, b0);
    fft_stage<false, 1024>(b0, b1);

    PwParams P;
    P.ra0 = rmat[(size_t)h0 * HID + h0];
    P.ia0 = imat[(size_t)h0 * HID + h0];
    P.ra1 = rmat[(size_t)h1 * HID + h1];
    P.ia1 = imat[(size_t)h1 * HID + h1];
    P.rb0 = rb[h0]; P.ib0 = ib[h0];
    P.rb1 = rb[h1]; P.ib1 = ib[h1];

    // inverse FFT with pointwise fused into stage 1's read; final stage
    // writes gmem (scaled, tf32-rounded)
    inv_stage1_pw(b1, b0, P);
    fft_stage<true, 4>(b0, b1);
    fft_stage<true, 16>(b1, b0);
    fft_stage<true, 64>(b0, b1);
    fft_stage<true, 256>(b1, b0);
    fft_stage6_inv_g(b0, row0, row1);
}

// ---------------------------------------------------------------------------
// GEMM2 (tf32, cp.async 3-stage): y[b,n,c] = BN( sum_h ht[b,h,n] * W2[c,h] )
// ---------------------------------------------------------------------------
#define G2_ASZ (16 * 264)
#define G2_WSZ (64 * 20)
#define G2_SSZ (G2_ASZ + G2_WSZ)
#define G2_SMEM (3 * G2_SSZ * 4)

__global__ __launch_bounds__(256) void gemm2_k(
    const float* __restrict__ g2, const float* __restrict__ b2,
    const float* __restrict__ m2, const float* __restrict__ v2,
    float* __restrict__ y)
{
    extern __shared__ uint32_t smem_u[];

    int tid  = threadIdx.x;
    int lane = tid & 31;
    int wid  = tid >> 5;
    int wm   = wid >> 1;
    int wn   = wid & 1;
    int lk   = lane & 3;
    int lg   = lane >> 2;

    int n0 = blockIdx.x * 256;
    int c0 = blockIdx.y * 64;
    int b  = blockIdx.z;

    const float* hp = g_ht + (size_t)b * HID * NTOK + n0;
    const float* wp = g_w2t + (size_t)c0 * HID;

    uint32_t sbase = (uint32_t)__cvta_generic_to_shared(smem_u);

    int arow = tid >> 6;
    int aoff = (tid & 63) << 2;
    int wrow = tid >> 2;
    int woff = (tid & 3) << 2;

#define G2_LOAD(st, kc)                                                          \
    {                                                                            \
        uint32_t ao = sbase + (st) * G2_SSZ * 4;                                 \
        uint32_t wo = ao + G2_ASZ * 4;                                           \
        _Pragma("unroll")                                                        \
        for (int i = 0; i < 4; i++) {                                            \
            int row = arow + i * 4;                                              \
            cp_async16(ao + (row * 264 + aoff) * 4,                              \
                       hp + (size_t)((kc) * 16 + row) * NTOK + aoff);            \
        }                                                                        \
        cp_async16(wo + (wrow * 20 + woff) * 4,                                  \
                   wp + (size_t)wrow * HID + (kc) * 16 + woff);                  \
    }

    float4 acc[4][4];
#pragma unroll
    for (int i = 0; i < 4; i++)
#pragma unroll
        for (int j = 0; j < 4; j++) acc[i][j] = make_float4(0.f, 0.f, 0.f, 0.f);

    G2_LOAD(0, 0); CP_COMMIT();
    G2_LOAD(1, 1); CP_COMMIT();

    for (int kc = 0; kc < 48; kc++) {
        CP_WAIT1();
        __syncthreads();
        if (kc + 2 < 48) { G2_LOAD((kc + 2) % 3, kc + 2); }
        CP_COMMIT();

        const uint32_t* sA = smem_u + (kc % 3) * G2_SSZ;
        const uint32_t* sW = sA + G2_ASZ;
#pragma unroll
        for (int k0 = 0; k0 < 16; k0 += 8) {
            uint32_t afr[4][4], bfr[4][2];
#pragma unroll
            for (int mf = 0; mf < 4; mf++) {
                int mb = wm * 64 + mf * 16 + lg;
                afr[mf][0] = sA[(k0 + lk    ) * 264 + mb    ];
                afr[mf][1] = sA[(k0 + lk    ) * 264 + mb + 8];
                afr[mf][2] = sA[(k0 + lk + 4) * 264 + mb    ];
                afr[mf][3] = sA[(k0 + lk + 4) * 264 + mb + 8];
            }
#pragma unroll
            for (int nf = 0; nf < 4; nf++) {
                int cb = wn * 32 + nf * 8 + lg;
                bfr[nf][0] = sW[cb * 20 + k0 + lk    ];
                bfr[nf][1] = sW[cb * 20 + k0 + lk + 4];
            }
#pragma unroll
            for (int mf = 0; mf < 4; mf++)
#pragma unroll
                for (int nf = 0; nf < 4; nf++)
                    mma_tf32(acc[mf][nf], afr[mf], bfr[nf]);
        }
    }

    float scv[4][2], shv[4][2];
#pragma unroll
    for (int nf = 0; nf < 4; nf++) {
        int c = c0 + wn * 32 + nf * 8 + 2 * lk;
#pragma unroll
        for (int j = 0; j < 2; j++) {
            scv[nf][j] = g2[c + j] * rsqrtf(v2[c + j] + EPSBN);
            shv[nf][j] = b2[c + j] - m2[c + j] * scv[nf][j];
        }
    }
#pragma unroll
    for (int mf = 0; mf < 4; mf++) {
        int n_r0 = n0 + wm * 64 + mf * 16 + lg;
        int n_r1 = n_r0 + 8;
        float* p0 = y + ((size_t)(b * NTOK + n_r0)) * CIN;
        float* p1 = y + ((size_t)(b * NTOK + n_r1)) * CIN;
#pragma unroll
        for (int nf = 0; nf < 4; nf++) {
            int c = c0 + wn * 32 + nf * 8 + 2 * lk;
            float4 a = acc[mf][nf];
            float2 o0, o1;
            o0.x = fmaf(a.x, scv[nf][0], shv[nf][0]);
            o0.y = fmaf(a.y, scv[nf][1], shv[nf][1]);
            o1.x = fmaf(a.z, scv[nf][0], shv[nf][0]);
            o1.y = fmaf(a.w, scv[nf][1], shv[nf][1]);
            *(float2*)(p0 + c) = o0;
            *(float2*)(p1 + c) = o1;
        }
    }
}

// ---------------------------------------------------------------------------
extern "C" void kernel_launch(void* const* d_in, const int* in_sizes, int n_in,
                              void* d_out, int out_size)
{
    const float* x  = (const float*)d_in[0];
    const float* W1 = (const float*)d_in[1];
    const float* g1 = (const float*)d_in[2];
    const float* b1 = (const float*)d_in[3];
    const float* m1 = (const float*)d_in[4];
    const float* v1 = (const float*)d_in[5];
    const float* r  = (const float*)d_in[6];
    const float* im = (const float*)d_in[7];
    const float* rb = (const float*)d_in[8];
    const float* ib = (const float*)d_in[9];
    const float* W2 = (const float*)d_in[10];
    const float* g2 = (const float*)d_in[11];
    const float* b2 = (const float*)d_in[12];
    const float* m2 = (const float*)d_in[13];
    const float* v2 = (const float*)d_in[14];
    float* y = (float*)d_out;

    static bool attr_set = false;
    if (!attr_set) {
        cudaFuncSetAttribute(fftmix_k, cudaFuncAttributeMaxDynamicSharedMemorySize,
                             2 * FFT_BUF * sizeof(float2));
        cudaFuncSetAttribute(gemm1_k, cudaFuncAttributeMaxDynamicSharedMemorySize, G1_SMEM);
        cudaFuncSetAttribute(gemm2_k, cudaFuncAttributeMaxDynamicSharedMemorySize, G2_SMEM);
        attr_set = true;
    }

    prep_k<<<(XT_N + 2 * W_N) / 4 / 256, 256>>>(x, W1, W2);
    twiddle_init_k<<<16, 256>>>();
    gemm1_k<<<dim3(NTOK / 128, HID / 128, BATCH), 256, G1_SMEM>>>(g1, b1, m1, v1);
    fftmix_k<<<BATCH * (HID / 2), 256, 2 * FFT_BUF * sizeof(float2)>>>(r, im, rb, ib);
    gemm2_k<<<dim3(NTOK / 256, CIN / 64, BATCH), 256, G2_SMEM>>>(g2, b2, m2, v2, y);
}

// round 16
// speedup vs baseline: 1.3874x; 1.0437x over previous
#include <cuda_runtime.h>
#include <cstdint>

#define BATCH 8
#define NTOK  4096
#define CIN   192
#define HID   768
#define EPSBN 1e-5f

#define XT_N (BATCH * NTOK * CIN)   // 6291456
#define W_N  (HID * CIN)            // 147456

// Scratch
__device__ float  g_ht[(size_t)BATCH * HID * NTOK];   // hidden, [B,H,N], ~100.7MB
__device__ float  g_xt[XT_N];                         // tf32-rounded x
__device__ float  g_w1t[W_N];                         // tf32-rounded W1
__device__ float  g_w2t[W_N];                         // tf32-rounded W2
__device__ float2 g_tw[NTOK];                         // forward twiddles

// XOR bank swizzle for FFT smem buffers: spreads stride-16 store groups
// across bank-pairs; bijective; keeps any aligned run of 4 consecutive
// indices consecutive (bits 0-1 untouched).
#define SW(i) ((i) ^ ((((i) >> 4) & 3) << 2))
#define FFT_BUF 4096

// ---------------------------------------------------------------------------
__device__ __forceinline__ float tf32r(float x)
{
    uint32_t r;
    asm("cvt.rna.tf32.f32 %0, %1;" : "=r"(r) : "f"(x));
    return __uint_as_float(r);
}

__device__ __forceinline__ void mma_tf32(float4& d, const uint32_t* a, const uint32_t* b)
{
    asm volatile(
        "mma.sync.aligned.m16n8k8.row.col.f32.tf32.tf32.f32 "
        "{%0,%1,%2,%3}, {%4,%5,%6,%7}, {%8,%9}, {%0,%1,%2,%3};"
        : "+f"(d.x), "+f"(d.y), "+f"(d.z), "+f"(d.w)
        : "r"(a[0]), "r"(a[1]), "r"(a[2]), "r"(a[3]), "r"(b[0]), "r"(b[1]));
}

__device__ __forceinline__ void cp_async16(uint32_t saddr, const void* gptr)
{
    asm volatile("cp.async.cg.shared.global [%0], [%1], 16;" :: "r"(saddr), "l"(gptr));
}
#define CP_COMMIT() asm volatile("cp.async.commit_group;")
#define CP_WAIT1()  asm volatile("cp.async.wait_group 1;")

// ---------------------------------------------------------------------------
__global__ void twiddle_init_k()
{
    int t = blockIdx.x * blockDim.x + threadIdx.x;
    if (t < NTOK) {
        float s, c;
        sincospif(-2.0f * (float)t / (float)NTOK, &s, &c);
        g_tw[t] = make_float2(c, s);
    }
}

// RN-round inputs to tf32 once (so GEMMs can feed raw bits losslessly)
__global__ void prep_k(const float* __restrict__ x, const float* __restrict__ W1,
                       const float* __restrict__ W2)
{
    int idx = blockIdx.x * blockDim.x + threadIdx.x;   // float4 index
    const float4* src;
    float4* dst;
    int off;
    if (idx < XT_N / 4)                 { src = (const float4*)x;  dst = (float4*)g_xt;  off = idx; }
    else if (idx < (XT_N + W_N) / 4)    { src = (const float4*)W1; dst = (float4*)g_w1t; off = idx - XT_N / 4; }
    else                                { src = (const float4*)W2; dst = (float4*)g_w2t; off = idx - (XT_N + W_N) / 4; }
    float4 v = src[off];
    v.x = tf32r(v.x); v.y = tf32r(v.y); v.z = tf32r(v.z); v.w = tf32r(v.w);
    dst[off] = v;
}

// ---------------------------------------------------------------------------
// GEMM1 (tf32, cp.async 3-stage): ht[b,h,n] = relu(BN( sum_c x[b,n,c]*W1[h,c] ))
// ---------------------------------------------------------------------------
#define G1_SSZ (128 * 20 * 2)
#define G1_SMEM (3 * G1_SSZ * 4)

__global__ __launch_bounds__(256) void gemm1_k(
    const float* __restrict__ g1, const float* __restrict__ b1,
    const float* __restrict__ m1, const float* __restrict__ v1)
{
    extern __shared__ uint32_t smem_u[];

    int tid  = threadIdx.x;
    int lane = tid & 31;
    int wid  = tid >> 5;
    int wm   = wid & 1;
    int wn   = wid >> 1;
    int lk   = lane & 3;
    int lg   = lane >> 2;

    int n0 = blockIdx.x * 128;
    int h0 = blockIdx.y * 128;
    int b  = blockIdx.z;

    const float* wp = g_w1t + (size_t)h0 * CIN;
    const float* xp = g_xt + ((size_t)b * NTOK + n0) * CIN;

    uint32_t sbase = (uint32_t)__cvta_generic_to_shared(smem_u);

    int lrow = tid >> 2;
    int lko  = (tid & 3) << 2;

#define G1_LOAD(st, kc)                                                          \
    {                                                                            \
        uint32_t ao = sbase + (st) * G1_SSZ * 4;                                 \
        uint32_t bo = ao + 128 * 20 * 4;                                         \
        _Pragma("unroll")                                                        \
        for (int i = 0; i < 2; i++) {                                            \
            int row = lrow + i * 64;                                             \
            cp_async16(ao + (row * 20 + lko) * 4, wp + (size_t)row * CIN + (kc) * 16 + lko); \
            cp_async16(bo + (row * 20 + lko) * 4, xp + (size_t)row * CIN + (kc) * 16 + lko); \
        }                                                                        \
    }

    float4 acc[4][4];
#pragma unroll
    for (int i = 0; i < 4; i++)
#pragma unroll
        for (int j = 0; j < 4; j++) acc[i][j] = make_float4(0.f, 0.f, 0.f, 0.f);

    G1_LOAD(0, 0); CP_COMMIT();
    G1_LOAD(1, 1); CP_COMMIT();

    for (int kc = 0; kc < 12; kc++) {
        CP_WAIT1();
        __syncthreads();
        if (kc + 2 < 12) { G1_LOAD((kc + 2) % 3, kc + 2); }
        CP_COMMIT();

        const uint32_t* sA = smem_u + (kc % 3) * G1_SSZ;
        const uint32_t* sB = sA + 128 * 20;
#pragma unroll
        for (int k0 = 0; k0 < 16; k0 += 8) {
            uint32_t afr[4][4], bfr[4][2];
#pragma unroll
            for (int mf = 0; mf < 4; mf++) {
                int mb = wm * 64 + mf * 16 + lg;
                afr[mf][0] = sA[(mb    ) * 20 + k0 + lk    ];
                afr[mf][1] = sA[(mb + 8) * 20 + k0 + lk    ];
                afr[mf][2] = sA[(mb    ) * 20 + k0 + lk + 4];
                afr[mf][3] = sA[(mb + 8) * 20 + k0 + lk + 4];
            }
#pragma unroll
            for (int nf = 0; nf < 4; nf++) {
                int nb = wn * 32 + nf * 8 + lg;
                bfr[nf][0] = sB[nb * 20 + k0 + lk    ];
                bfr[nf][1] = sB[nb * 20 + k0 + lk + 4];
            }
#pragma unroll
            for (int mf = 0; mf < 4; mf++)
#pragma unroll
                for (int nf = 0; nf < 4; nf++)
                    mma_tf32(acc[mf][nf], afr[mf], bfr[nf]);
        }
    }

#pragma unroll
    for (int mf = 0; mf < 4; mf++) {
        int h_r0 = h0 + wm * 64 + mf * 16 + lg;
        int h_r1 = h_r0 + 8;
        float sc0 = g1[h_r0] * rsqrtf(v1[h_r0] + EPSBN);
        float sh0 = b1[h_r0] - m1[h_r0] * sc0;
        float sc1 = g1[h_r1] * rsqrtf(v1[h_r1] + EPSBN);
        float sh1 = b1[h_r1] - m1[h_r1] * sc1;
        float* p0 = g_ht + ((size_t)(b * HID + h_r0)) * NTOK + n0;
        float* p1 = g_ht + ((size_t)(b * HID + h_r1)) * NTOK + n0;
#pragma unroll
        for (int nf = 0; nf < 4; nf++) {
            int nc = wn * 32 + nf * 8 + 2 * lk;
            float4 a = acc[mf][nf];
            float2 o0, o1;
            o0.x = fmaxf(fmaf(a.x, sc0, sh0), 0.0f);
            o0.y = fmaxf(fmaf(a.y, sc0, sh0), 0.0f);
            o1.x = fmaxf(fmaf(a.z, sc1, sh1), 0.0f);
            o1.y = fmaxf(fmaf(a.w, sc1, sh1), 0.0f);
            *(float2*)(p0 + nc) = o0;
            *(float2*)(p1 + nc) = o1;
        }
    }
}

// ---------------------------------------------------------------------------
// Fused FFT -> pointwise -> IFFT. Radix-4 Stockham, 256 threads, gmem-fused
// end stages, single twiddle load per butterfly, XOR-swizzled smem (conflict-
// free stores on all stages; scatter stages use float4 store pairs).
// ---------------------------------------------------------------------------
__device__ __forceinline__ float2 cmulf(float2 a, float2 b)
{
    return make_float2(fmaf(a.x, b.x, -a.y * b.y), fmaf(a.x, b.y, a.y * b.x));
}

template <bool INV>
__device__ __forceinline__ void r4bf(float2 a0, float2 a1, float2 a2, float2 a3,
                                     float2& X0, float2& X1, float2& X2, float2& X3)
{
    float2 t0 = make_float2(a0.x + a2.x, a0.y + a2.y);
    float2 t1 = make_float2(a0.x - a2.x, a0.y - a2.y);
    float2 t2 = make_float2(a1.x + a3.x, a1.y + a3.y);
    float2 u  = make_float2(a1.x - a3.x, a1.y - a3.y);
    float2 t3 = INV ? make_float2(-u.y, u.x) : make_float2(u.y, -u.x);
    X0 = make_float2(t0.x + t2.x, t0.y + t2.y);
    X1 = make_float2(t1.x + t3.x, t1.y + t3.y);
    X2 = make_float2(t0.x - t2.x, t0.y - t2.y);
    X3 = make_float2(t1.x - t3.x, t1.y - t3.y);
}

// store 4 consecutive float2 (base % 4 == 0) as two float4s (swizzle-safe)
__device__ __forceinline__ void st4(float2* __restrict__ dst, int base,
                                    float2 X0, float2 X1, float2 X2, float2 X3)
{
    int sb = SW(base);
    *(float4*)(&dst[sb    ]) = make_float4(X0.x, X0.y, X1.x, X1.y);
    *(float4*)(&dst[sb + 2]) = make_float4(X2.x, X2.y, X3.x, X3.y);
}

template <bool INV, int NS>
__device__ __forceinline__ void fft_stage(const float2* __restrict__ src,
                                          float2* __restrict__ dst)
{
    constexpr int STEP = (NTOK / 4) / NS;
#pragma unroll
    for (int q = 0; q < 4; q++) {
        int j = threadIdx.x + q * 256;
        int k = j & (NS - 1);
        float2 a0 = src[SW(j)];
        float2 a1 = src[SW(j + 1024)];
        float2 a2 = src[SW(j + 2048)];
        float2 a3 = src[SW(j + 3072)];
        if (NS > 1) {
            float2 w1 = g_tw[k * STEP];
            if (INV) w1.y = -w1.y;
            float2 w2 = cmulf(w1, w1);
            float2 w3 = cmulf(w1, w2);
            a1 = cmulf(w1, a1);
            a2 = cmulf(w2, a2);
            a3 = cmulf(w3, a3);
        }
        float2 X0, X1, X2, X3;
        r4bf<INV>(a0, a1, a2, a3, X0, X1, X2, X3);
        int base = ((j - k) << 2) + k;
        dst[SW(base         )] = X0;
        dst[SW(base +     NS)] = X1;
        dst[SW(base + 2 * NS)] = X2;
        dst[SW(base + 3 * NS)] = X3;
    }
    __syncthreads();
}

// forward stage 1 (NS=1, no twiddles) reading directly from the two real rows
__device__ __forceinline__ void fft_stage1_g(const float* __restrict__ row0,
                                             const float* __restrict__ row1,
                                             float2* __restrict__ dst)
{
#pragma unroll
    for (int q = 0; q < 4; q++) {
        int j = threadIdx.x + q * 256;
        float2 a0 = make_float2(row0[j       ], row1[j       ]);
        float2 a1 = make_float2(row0[j + 1024], row1[j + 1024]);
        float2 a2 = make_float2(row0[j + 2048], row1[j + 2048]);
        float2 a3 = make_float2(row0[j + 3072], row1[j + 3072]);
        float2 X0, X1, X2, X3;
        r4bf<false>(a0, a1, a2, a3, X0, X1, X2, X3);
        st4(dst, j << 2, X0, X1, X2, X3);
    }
    __syncthreads();
}

// pointwise for one packed-pair spectrum element:
// given Zk = Z[P] and Zm = Z[(N-P) mod N], returns T[P] (repacked, scaled)
struct PwParams {
    float ra0, ia0, ra1, ia1, rb0, ib0, rb1, ib1;
};

__device__ __forceinline__ float2 pw_elem(float2 Zk, float2 Zm, const PwParams& P)
{
    const float hv = 0.5f * 0.015625f;   // 0.5 / sqrt(4096)
    float2 X0k = make_float2((Zk.x + Zm.x) * hv, (Zk.y - Zm.y) * hv);
    float2 X1k = make_float2((Zk.y + Zm.y) * hv, (Zm.x - Zk.x) * hv);
    float2 X0m = make_float2((Zm.x + Zk.x) * hv, (Zm.y - Zk.y) * hv);
    float2 X1m = make_float2((Zm.y + Zk.y) * hv, (Zk.x - Zm.x) * hv);

    float2 S0k, S0m, S1k, S1m;
    S0k.x = fmaxf(fmaf(P.ra0, X0k.x, fmaf(-P.ia0, X0k.y, P.rb0)), 0.0f);
    S0k.y = fmaxf(fmaf(P.ra0, X0k.y, fmaf( P.ia0, X0k.x, P.ib0)), 0.0f);
    S0m.x = fmaxf(fmaf(P.ra0, X0m.x, fmaf(-P.ia0, X0m.y, P.rb0)), 0.0f);
    S0m.y = fmaxf(fmaf(P.ra0, X0m.y, fmaf( P.ia0, X0m.x, P.ib0)), 0.0f);
    S1k.x = fmaxf(fmaf(P.ra1, X1k.x, fmaf(-P.ia1, X1k.y, P.rb1)), 0.0f);
    S1k.y = fmaxf(fmaf(P.ra1, X1k.y, fmaf( P.ia1, X1k.x, P.ib1)), 0.0f);
    S1m.x = fmaxf(fmaf(P.ra1, X1m.x, fmaf(-P.ia1, X1m.y, P.rb1)), 0.0f);
    S1m.y = fmaxf(fmaf(P.ra1, X1m.y, fmaf( P.ia1, X1m.x, P.ib1)), 0.0f);

    // Hermitian projection: H[k] = (S[k] + conj(S[m])) / 2 ; T = H0 + i*H1
    float2 H0 = make_float2(0.5f * (S0k.x + S0m.x), 0.5f * (S0k.y - S0m.y));
    float2 H1 = make_float2(0.5f * (S1k.x + S1m.x), 0.5f * (S1k.y - S1m.y));
    return make_float2(H0.x - H1.y, H0.y + H1.x);
}

// inverse stage 1 (NS=1) with the pointwise fused into the read.
// thread element positions {j, j+1024, j+2048, j+3072}; Hermitian partners
// are {(4096-j)&4095, 3072-j, 2048-j, 1024-j} (self-pairs handled by formula).
__device__ __forceinline__ void inv_stage1_pw(const float2* __restrict__ src,
                                              float2* __restrict__ dst,
                                              const PwParams& P)
{
#pragma unroll
    for (int q = 0; q < 4; q++) {
        int j = threadIdx.x + q * 256;      // 0..1023
        float2 Z0 = src[SW(j)];
        float2 Z1 = src[SW(j + 1024)];
        float2 Z2 = src[SW(j + 2048)];
        float2 Z3 = src[SW(j + 3072)];
        int m0 = (NTOK - j) & (NTOK - 1);
        float2 M0 = src[SW(m0)];
        float2 M1 = src[SW(3072 - j)];
        float2 M2 = src[SW(2048 - j)];
        float2 M3 = src[SW(1024 - j)];

        float2 a0 = pw_elem(Z0, M0, P);
        float2 a1 = pw_elem(Z1, M1, P);
        float2 a2 = pw_elem(Z2, M2, P);
        float2 a3 = pw_elem(Z3, M3, P);

        float2 X0, X1, X2, X3;
        r4bf<true>(a0, a1, a2, a3, X0, X1, X2, X3);
        st4(dst, j << 2, X0, X1, X2, X3);
    }
    __syncthreads();
}

// inverse stage 6 (NS=1024): outputs are coalesced -> write gmem directly
__device__ __forceinline__ void fft_stage6_inv_g(const float2* __restrict__ src,
                                                 float* __restrict__ row0,
                                                 float* __restrict__ row1)
{
    const float inv = 0.015625f;        // 1/sqrt(4096)
#pragma unroll
    for (int q = 0; q < 4; q++) {
        int j = threadIdx.x + q * 256;  // 0..1023 ; k = j, base = j
        float2 a0 = src[SW(j)];
        float2 a1 = src[SW(j + 1024)];
        float2 a2 = src[SW(j + 2048)];
        float2 a3 = src[SW(j + 3072)];
        float2 w1 = g_tw[j];
        w1.y = -w1.y;                   // inverse
        float2 w2 = cmulf(w1, w1);
        float2 w3 = cmulf(w1, w2);
        a1 = cmulf(w1, a1);
        a2 = cmulf(w2, a2);
        a3 = cmulf(w3, a3);
        float2 X0, X1, X2, X3;
        r4bf<true>(a0, a1, a2, a3, X0, X1, X2, X3);
        row0[j       ] = tf32r(X0.x * inv);
        row1[j       ] = tf32r(X0.y * inv);
        row0[j + 1024] = tf32r(X1.x * inv);
        row1[j + 1024] = tf32r(X1.y * inv);
        row0[j + 2048] = tf32r(X2.x * inv);
        row1[j + 2048] = tf32r(X2.y * inv);
        row0[j + 3072] = tf32r(X3.x * inv);
        row1[j + 3072] = tf32r(X3.y * inv);
    }
}

__global__ __launch_bounds__(256) void fftmix_k(
    const float* __restrict__ rmat, const float* __restrict__ imat,
    const float* __restrict__ rb,   const float* __restrict__ ib)
{
    extern __shared__ float2 sb[];
    float2* b0 = sb;
    float2* b1 = sb + FFT_BUF;

    int blk = blockIdx.x;
    int b   = blk / (HID / 2);
    int hp  = blk % (HID / 2);
    int h0  = 2 * hp;
    int h1  = h0 + 1;
    float* row0 = g_ht + ((size_t)(b * HID + h0)) * NTOK;
    float* row1 = row0 + NTOK;

    // forward FFT: gmem -> b0, then 5 smem stages; Z ends in b1
    fft_stage1_g(row0, row1, b0);
    fft_stage<false, 4>(b0, b1);
    fft_stage<false, 16>(b1, b0);
    fft_stage<false, 64>(b0, b1);
    fft_stage<false, 256>(b1, b0);
    fft_stage<false, 1024>(b0, b1);

    PwParams P;
    P.ra0 = rmat[(size_t)h0 * HID + h0];
    P.ia0 = imat[(size_t)h0 * HID + h0];
    P.ra1 = rmat[(size_t)h1 * HID + h1];
    P.ia1 = imat[(size_t)h1 * HID + h1];
    P.rb0 = rb[h0]; P.ib0 = ib[h0];
    P.rb1 = rb[h1]; P.ib1 = ib[h1];

    // inverse FFT with pointwise fused into stage 1's read; final stage
    // writes gmem (scaled, tf32-rounded)
    inv_stage1_pw(b1, b0, P);
    fft_stage<true, 4>(b0, b1);
    fft_stage<true, 16>(b1, b0);
    fft_stage<true, 64>(b0, b1);
    fft_stage<true, 256>(b1, b0);
    fft_stage6_inv_g(b0, row0, row1);
}

// ---------------------------------------------------------------------------
// GEMM2 (tf32, cp.async 3-stage): y[b,n,c] = BN( sum_h ht[b,h,n] * W2[c,h] )
// ---------------------------------------------------------------------------
#define G2_ASZ (16 * 264)
#define G2_WSZ (64 * 20)
#define G2_SSZ (G2_ASZ + G2_WSZ)
#define G2_SMEM (3 * G2_SSZ * 4)

__global__ __launch_bounds__(256) void gemm2_k(
    const float* __restrict__ g2, const float* __restrict__ b2,
    const float* __restrict__ m2, const float* __restrict__ v2,
    float* __restrict__ y)
{
    extern __shared__ uint32_t smem_u[];

    int tid  = threadIdx.x;
    int lane = tid & 31;
    int wid  = tid >> 5;
    int wm   = wid >> 1;
    int wn   = wid & 1;
    int lk   = lane & 3;
    int lg   = lane >> 2;

    int n0 = blockIdx.x * 256;
    int c0 = blockIdx.y * 64;
    int b  = blockIdx.z;

    const float* hp = g_ht + (size_t)b * HID * NTOK + n0;
    const float* wp = g_w2t + (size_t)c0 * HID;

    uint32_t sbase = (uint32_t)__cvta_generic_to_shared(smem_u);

    int arow = tid >> 6;
    int aoff = (tid & 63) << 2;
    int wrow = tid >> 2;
    int woff = (tid & 3) << 2;

#define G2_LOAD(st, kc)                                                          \
    {                                                                            \
        uint32_t ao = sbase + (st) * G2_SSZ * 4;                                 \
        uint32_t wo = ao + G2_ASZ * 4;                                           \
        _Pragma("unroll")                                                        \
        for (int i = 0; i < 4; i++) {                                            \
            int row = arow + i * 4;                                              \
            cp_async16(ao + (row * 264 + aoff) * 4,                              \
                       hp + (size_t)((kc) * 16 + row) * NTOK + aoff);            \
        }                                                                        \
        cp_async16(wo + (wrow * 20 + woff) * 4,                                  \
                   wp + (size_t)wrow * HID + (kc) * 16 + woff);                  \
    }

    float4 acc[4][4];
#pragma unroll
    for (int i = 0; i < 4; i++)
#pragma unroll
        for (int j = 0; j < 4; j++) acc[i][j] = make_float4(0.f, 0.f, 0.f, 0.f);

    G2_LOAD(0, 0); CP_COMMIT();
    G2_LOAD(1, 1); CP_COMMIT();

    for (int kc = 0; kc < 48; kc++) {
        CP_WAIT1();
        __syncthreads();
        if (kc + 2 < 48) { G2_LOAD((kc + 2) % 3, kc + 2); }
        CP_COMMIT();

        const uint32_t* sA = smem_u + (kc % 3) * G2_SSZ;
        const uint32_t* sW = sA + G2_ASZ;
#pragma unroll
        for (int k0 = 0; k0 < 16; k0 += 8) {
            uint32_t afr[4][4], bfr[4][2];
#pragma unroll
            for (int mf = 0; mf < 4; mf++) {
                int mb = wm * 64 + mf * 16 + lg;
                afr[mf][0] = sA[(k0 + lk    ) * 264 + mb    ];
                afr[mf][1] = sA[(k0 + lk    ) * 264 + mb + 8];
                afr[mf][2] = sA[(k0 + lk + 4) * 264 + mb    ];
                afr[mf][3] = sA[(k0 + lk + 4) * 264 + mb + 8];
            }
#pragma unroll
            for (int nf = 0; nf < 4; nf++) {
                int cb = wn * 32 + nf * 8 + lg;
                bfr[nf][0] = sW[cb * 20 + k0 + lk    ];
                bfr[nf][1] = sW[cb * 20 + k0 + lk + 4];
            }
#pragma unroll
            for (int mf = 0; mf < 4; mf++)
#pragma unroll
                for (int nf = 0; nf < 4; nf++)
                    mma_tf32(acc[mf][nf], afr[mf], bfr[nf]);
        }
    }

    float scv[4][2], shv[4][2];
#pragma unroll
    for (int nf = 0; nf < 4; nf++) {
        int c = c0 + wn * 32 + nf * 8 + 2 * lk;
#pragma unroll
        for (int j = 0; j < 2; j++) {
            scv[nf][j] = g2[c + j] * rsqrtf(v2[c + j] + EPSBN);
            shv[nf][j] = b2[c + j] - m2[c + j] * scv[nf][j];
        }
    }
#pragma unroll
    for (int mf = 0; mf < 4; mf++) {
        int n_r0 = n0 + wm * 64 + mf * 16 + lg;
        int n_r1 = n_r0 + 8;
        float* p0 = y + ((size_t)(b * NTOK + n_r0)) * CIN;
        float* p1 = y + ((size_t)(b * NTOK + n_r1)) * CIN;
#pragma unroll
        for (int nf = 0; nf < 4; nf++) {
            int c = c0 + wn * 32 + nf * 8 + 2 * lk;
            float4 a = acc[mf][nf];
            float2 o0, o1;
            o0.x = fmaf(a.x, scv[nf][0], shv[nf][0]);
            o0.y = fmaf(a.y, scv[nf][1], shv[nf][1]);
            o1.x = fmaf(a.z, scv[nf][0], shv[nf][0]);
            o1.y = fmaf(a.w, scv[nf][1], shv[nf][1]);
            *(float2*)(p0 + c) = o0;
            *(float2*)(p1 + c) = o1;
        }
    }
}

// ---------------------------------------------------------------------------
extern "C" void kernel_launch(void* const* d_in, const int* in_sizes, int n_in,
                              void* d_out, int out_size)
{
    const float* x  = (const float*)d_in[0];
    const float* W1 = (const float*)d_in[1];
    const float* g1 = (const float*)d_in[2];
    const float* b1 = (const float*)d_in[3];
    const float* m1 = (const float*)d_in[4];
    const float* v1 = (const float*)d_in[5];
    const float* r  = (const float*)d_in[6];
    const float* im = (const float*)d_in[7];
    const float* rb = (const float*)d_in[8];
    const float* ib = (const float*)d_in[9];
    const float* W2 = (const float*)d_in[10];
    const float* g2 = (const float*)d_in[11];
    const float* b2 = (const float*)d_in[12];
    const float* m2 = (const float*)d_in[13];
    const float* v2 = (const float*)d_in[14];
    float* y = (float*)d_out;

    static bool attr_set = false;
    if (!attr_set) {
        cudaFuncSetAttribute(fftmix_k, cudaFuncAttributeMaxDynamicSharedMemorySize,
                             2 * FFT_BUF * sizeof(float2));
        cudaFuncSetAttribute(gemm1_k, cudaFuncAttributeMaxDynamicSharedMemorySize, G1_SMEM);
        cudaFuncSetAttribute(gemm2_k, cudaFuncAttributeMaxDynamicSharedMemorySize, G2_SMEM);
        attr_set = true;
    }

    prep_k<<<(XT_N + 2 * W_N) / 4 / 256, 256>>>(x, W1, W2);
    twiddle_init_k<<<16, 256>>>();
    gemm1_k<<<dim3(NTOK / 128, HID / 128, BATCH), 256, G1_SMEM>>>(g1, b1, m1, v1);
    fftmix_k<<<BATCH * (HID / 2), 256, 2 * FFT_BUF * sizeof(float2)>>>(r, im, rb, ib);
    gemm2_k<<<dim3(NTOK / 256, CIN / 64, BATCH), 256, G2_SMEM>>>(g2, b2, m2, v2, y);
}

// round 17
// speedup vs baseline: 1.4678x; 1.0580x over previous
#include <cuda_runtime.h>
#include <cstdint>

#define BATCH 8
#define NTOK  4096
#define CIN   192
#define HID   768
#define EPSBN 1e-5f

// Scratch
__device__ float  g_ht[(size_t)BATCH * HID * NTOK];   // hidden, [B,H,N], ~100.7MB
__device__ float2 g_tw[NTOK];                         // forward twiddles

// XOR bank swizzle for FFT smem buffers
#define SW(i) ((i) ^ ((((i) >> 4) & 3) << 2))
#define FFT_BUF 4096

// ---------------------------------------------------------------------------
__device__ __forceinline__ float tf32r(float x)
{
    uint32_t r;
    asm("cvt.rna.tf32.f32 %0, %1;" : "=r"(r) : "f"(x));
    return __uint_as_float(r);
}

__device__ __forceinline__ void mma_tf32(float4& d, const uint32_t* a, const uint32_t* b)
{
    asm volatile(
        "mma.sync.aligned.m16n8k8.row.col.f32.tf32.tf32.f32 "
        "{%0,%1,%2,%3}, {%4,%5,%6,%7}, {%8,%9}, {%0,%1,%2,%3};"
        : "+f"(d.x), "+f"(d.y), "+f"(d.z), "+f"(d.w)
        : "r"(a[0]), "r"(a[1]), "r"(a[2]), "r"(a[3]), "r"(b[0]), "r"(b[1]));
}

__device__ __forceinline__ void cp_async16(uint32_t saddr, const void* gptr)
{
    asm volatile("cp.async.cg.shared.global [%0], [%1], 16;" :: "r"(saddr), "l"(gptr));
}
#define CP_COMMIT() asm volatile("cp.async.commit_group;")
#define CP_WAIT2()  asm volatile("cp.async.wait_group 2;")
#define CP_WAIT3()  asm volatile("cp.async.wait_group 3;")

// ---------------------------------------------------------------------------
__global__ void twiddle_init_k()
{
    int t = blockIdx.x * blockDim.x + threadIdx.x;
    if (t < NTOK) {
        float s, c;
        sincospif(-2.0f * (float)t / (float)NTOK, &s, &c);
        g_tw[t] = make_float2(c, s);
    }
}

// ---------------------------------------------------------------------------
// GEMM1 (tf32, cp.async 4-stage): ht[b,h,n] = relu(BN( sum_c x[b,n,c]*W1[h,c] ))
// Raw fp32 operands (tf32 MMA truncates mantissa in HW).
// ---------------------------------------------------------------------------
#define G1_SSZ (128 * 20 * 2)
#define G1_DEPTH 4
#define G1_SMEM (G1_DEPTH * G1_SSZ * 4)

__global__ __launch_bounds__(256) void gemm1_k(
    const float* __restrict__ x,  const float* __restrict__ W1,
    const float* __restrict__ g1, const float* __restrict__ b1,
    const float* __restrict__ m1, const float* __restrict__ v1)
{
    extern __shared__ uint32_t smem_u[];

    int tid  = threadIdx.x;
    int lane = tid & 31;
    int wid  = tid >> 5;
    int wm   = wid & 1;
    int wn   = wid >> 1;
    int lk   = lane & 3;
    int lg   = lane >> 2;

    int n0 = blockIdx.x * 128;
    int h0 = blockIdx.y * 128;
    int b  = blockIdx.z;

    const float* wp = W1 + (size_t)h0 * CIN;
    const float* xp = x  + ((size_t)b * NTOK + n0) * CIN;

    uint32_t sbase = (uint32_t)__cvta_generic_to_shared(smem_u);

    int lrow = tid >> 2;
    int lko  = (tid & 3) << 2;

#define G1_LOAD(st, kc)                                                          \
    {                                                                            \
        uint32_t ao = sbase + (st) * G1_SSZ * 4;                                 \
        uint32_t bo = ao + 128 * 20 * 4;                                         \
        _Pragma("unroll")                                                        \
        for (int i = 0; i < 2; i++) {                                            \
            int row = lrow + i * 64;                                             \
            cp_async16(ao + (row * 20 + lko) * 4, wp + (size_t)row * CIN + (kc) * 16 + lko); \
            cp_async16(bo + (row * 20 + lko) * 4, xp + (size_t)row * CIN + (kc) * 16 + lko); \
        }                                                                        \
    }

    float4 acc[4][4];
#pragma unroll
    for (int i = 0; i < 4; i++)
#pragma unroll
        for (int j = 0; j < 4; j++) acc[i][j] = make_float4(0.f, 0.f, 0.f, 0.f);

    G1_LOAD(0, 0); CP_COMMIT();
    G1_LOAD(1, 1); CP_COMMIT();
    G1_LOAD(2, 2); CP_COMMIT();

    for (int kc = 0; kc < 12; kc++) {
        CP_WAIT2();
        __syncthreads();
        if (kc + 3 < 12) { G1_LOAD((kc + 3) % G1_DEPTH, kc + 3); }
        CP_COMMIT();

        const uint32_t* sA = smem_u + (kc % G1_DEPTH) * G1_SSZ;
        const uint32_t* sB = sA + 128 * 20;
#pragma unroll
        for (int k0 = 0; k0 < 16; k0 += 8) {
            uint32_t afr[4][4], bfr[4][2];
#pragma unroll
            for (int mf = 0; mf < 4; mf++) {
                int mb = wm * 64 + mf * 16 + lg;
                afr[mf][0] = sA[(mb    ) * 20 + k0 + lk    ];
                afr[mf][1] = sA[(mb + 8) * 20 + k0 + lk    ];
                afr[mf][2] = sA[(mb    ) * 20 + k0 + lk + 4];
                afr[mf][3] = sA[(mb + 8) * 20 + k0 + lk + 4];
            }
#pragma unroll
            for (int nf = 0; nf < 4; nf++) {
                int nb = wn * 32 + nf * 8 + lg;
                bfr[nf][0] = sB[nb * 20 + k0 + lk    ];
                bfr[nf][1] = sB[nb * 20 + k0 + lk + 4];
            }
#pragma unroll
            for (int mf = 0; mf < 4; mf++)
#pragma unroll
                for (int nf = 0; nf < 4; nf++)
                    mma_tf32(acc[mf][nf], afr[mf], bfr[nf]);
        }
    }

#pragma unroll
    for (int mf = 0; mf < 4; mf++) {
        int h_r0 = h0 + wm * 64 + mf * 16 + lg;
        int h_r1 = h_r0 + 8;
        float sc0 = g1[h_r0] * rsqrtf(v1[h_r0] + EPSBN);
        float sh0 = b1[h_r0] - m1[h_r0] * sc0;
        float sc1 = g1[h_r1] * rsqrtf(v1[h_r1] + EPSBN);
        float sh1 = b1[h_r1] - m1[h_r1] * sc1;
        float* p0 = g_ht + ((size_t)(b * HID + h_r0)) * NTOK + n0;
        float* p1 = g_ht + ((size_t)(b * HID + h_r1)) * NTOK + n0;
#pragma unroll
        for (int nf = 0; nf < 4; nf++) {
            int nc = wn * 32 + nf * 8 + 2 * lk;
            float4 a = acc[mf][nf];
            float2 o0, o1;
            o0.x = fmaxf(fmaf(a.x, sc0, sh0), 0.0f);
            o0.y = fmaxf(fmaf(a.y, sc0, sh0), 0.0f);
            o1.x = fmaxf(fmaf(a.z, sc1, sh1), 0.0f);
            o1.y = fmaxf(fmaf(a.w, sc1, sh1), 0.0f);
            *(float2*)(p0 + nc) = o0;
            *(float2*)(p1 + nc) = o1;
        }
    }
}

// ---------------------------------------------------------------------------
// Fused FFT -> pointwise -> IFFT. Radix-4 Stockham, 256 threads, gmem-fused
// end stages, single twiddle load per butterfly, XOR-swizzled smem.
// ---------------------------------------------------------------------------
__device__ __forceinline__ float2 cmulf(float2 a, float2 b)
{
    return make_float2(fmaf(a.x, b.x, -a.y * b.y), fmaf(a.x, b.y, a.y * b.x));
}

template <bool INV>
__device__ __forceinline__ void r4bf(float2 a0, float2 a1, float2 a2, float2 a3,
                                     float2& X0, float2& X1, float2& X2, float2& X3)
{
    float2 t0 = make_float2(a0.x + a2.x, a0.y + a2.y);
    float2 t1 = make_float2(a0.x - a2.x, a0.y - a2.y);
    float2 t2 = make_float2(a1.x + a3.x, a1.y + a3.y);
    float2 u  = make_float2(a1.x - a3.x, a1.y - a3.y);
    float2 t3 = INV ? make_float2(-u.y, u.x) : make_float2(u.y, -u.x);
    X0 = make_float2(t0.x + t2.x, t0.y + t2.y);
    X1 = make_float2(t1.x + t3.x, t1.y + t3.y);
    X2 = make_float2(t0.x - t2.x, t0.y - t2.y);
    X3 = make_float2(t1.x - t3.x, t1.y - t3.y);
}

// store 4 consecutive float2 (base % 4 == 0) as two float4s (swizzle-safe)
__device__ __forceinline__ void st4(float2* __restrict__ dst, int base,
                                    float2 X0, float2 X1, float2 X2, float2 X3)
{
    int sb = SW(base);
    *(float4*)(&dst[sb    ]) = make_float4(X0.x, X0.y, X1.x, X1.y);
    *(float4*)(&dst[sb + 2]) = make_float4(X2.x, X2.y, X3.x, X3.y);
}

template <bool INV, int NS>
__device__ __forceinline__ void fft_stage(const float2* __restrict__ src,
                                          float2* __restrict__ dst)
{
    constexpr int STEP = (NTOK / 4) / NS;
#pragma unroll
    for (int q = 0; q < 4; q++) {
        int j = threadIdx.x + q * 256;
        int k = j & (NS - 1);
        float2 a0 = src[SW(j)];
        float2 a1 = src[SW(j + 1024)];
        float2 a2 = src[SW(j + 2048)];
        float2 a3 = src[SW(j + 3072)];
        if (NS > 1) {
            float2 w1 = g_tw[k * STEP];
            if (INV) w1.y = -w1.y;
            float2 w2 = cmulf(w1, w1);
            float2 w3 = cmulf(w1, w2);
            a1 = cmulf(w1, a1);
            a2 = cmulf(w2, a2);
            a3 = cmulf(w3, a3);
        }
        float2 X0, X1, X2, X3;
        r4bf<INV>(a0, a1, a2, a3, X0, X1, X2, X3);
        int base = ((j - k) << 2) + k;
        dst[SW(base         )] = X0;
        dst[SW(base +     NS)] = X1;
        dst[SW(base + 2 * NS)] = X2;
        dst[SW(base + 3 * NS)] = X3;
    }
    __syncthreads();
}

// forward stage 1 (NS=1, no twiddles) reading directly from the two real rows
__device__ __forceinline__ void fft_stage1_g(const float* __restrict__ row0,
                                             const float* __restrict__ row1,
                                             float2* __restrict__ dst)
{
#pragma unroll
    for (int q = 0; q < 4; q++) {
        int j = threadIdx.x + q * 256;
        float2 a0 = make_float2(row0[j       ], row1[j       ]);
        float2 a1 = make_float2(row0[j + 1024], row1[j + 1024]);
        float2 a2 = make_float2(row0[j + 2048], row1[j + 2048]);
        float2 a3 = make_float2(row0[j + 3072], row1[j + 3072]);
        float2 X0, X1, X2, X3;
        r4bf<false>(a0, a1, a2, a3, X0, X1, X2, X3);
        st4(dst, j << 2, X0, X1, X2, X3);
    }
    __syncthreads();
}

// pointwise for one packed-pair spectrum element
struct PwParams {
    float ra0, ia0, ra1, ia1, rb0, ib0, rb1, ib1;
};

__device__ __forceinline__ float2 pw_elem(float2 Zk, float2 Zm, const PwParams& P)
{
    const float hv = 0.5f * 0.015625f;   // 0.5 / sqrt(4096)
    float2 X0k = make_float2((Zk.x + Zm.x) * hv, (Zk.y - Zm.y) * hv);
    float2 X1k = make_float2((Zk.y + Zm.y) * hv, (Zm.x - Zk.x) * hv);
    float2 X0m = make_float2((Zm.x + Zk.x) * hv, (Zm.y - Zk.y) * hv);
    float2 X1m = make_float2((Zm.y + Zk.y) * hv, (Zk.x - Zm.x) * hv);

    float2 S0k, S0m, S1k, S1m;
    S0k.x = fmaxf(fmaf(P.ra0, X0k.x, fmaf(-P.ia0, X0k.y, P.rb0)), 0.0f);
    S0k.y = fmaxf(fmaf(P.ra0, X0k.y, fmaf( P.ia0, X0k.x, P.ib0)), 0.0f);
    S0m.x = fmaxf(fmaf(P.ra0, X0m.x, fmaf(-P.ia0, X0m.y, P.rb0)), 0.0f);
    S0m.y = fmaxf(fmaf(P.ra0, X0m.y, fmaf( P.ia0, X0m.x, P.ib0)), 0.0f);
    S1k.x = fmaxf(fmaf(P.ra1, X1k.x, fmaf(-P.ia1, X1k.y, P.rb1)), 0.0f);
    S1k.y = fmaxf(fmaf(P.ra1, X1k.y, fmaf( P.ia1, X1k.x, P.ib1)), 0.0f);
    S1m.x = fmaxf(fmaf(P.ra1, X1m.x, fmaf(-P.ia1, X1m.y, P.rb1)), 0.0f);
    S1m.y = fmaxf(fmaf(P.ra1, X1m.y, fmaf( P.ia1, X1m.x, P.ib1)), 0.0f);

    float2 H0 = make_float2(0.5f * (S0k.x + S0m.x), 0.5f * (S0k.y - S0m.y));
    float2 H1 = make_float2(0.5f * (S1k.x + S1m.x), 0.5f * (S1k.y - S1m.y));
    return make_float2(H0.x - H1.y, H0.y + H1.x);
}

// inverse stage 1 (NS=1) with the pointwise fused into the read
__device__ __forceinline__ void inv_stage1_pw(const float2* __restrict__ src,
                                              float2* __restrict__ dst,
                                              const PwParams& P)
{
#pragma unroll
    for (int q = 0; q < 4; q++) {
        int j = threadIdx.x + q * 256;      // 0..1023
        float2 Z0 = src[SW(j)];
        float2 Z1 = src[SW(j + 1024)];
        float2 Z2 = src[SW(j + 2048)];
        float2 Z3 = src[SW(j + 3072)];
        int m0 = (NTOK - j) & (NTOK - 1);
        float2 M0 = src[SW(m0)];
        float2 M1 = src[SW(3072 - j)];
        float2 M2 = src[SW(2048 - j)];
        float2 M3 = src[SW(1024 - j)];

        float2 a0 = pw_elem(Z0, M0, P);
        float2 a1 = pw_elem(Z1, M1, P);
        float2 a2 = pw_elem(Z2, M2, P);
        float2 a3 = pw_elem(Z3, M3, P);

        float2 X0, X1, X2, X3;
        r4bf<true>(a0, a1, a2, a3, X0, X1, X2, X3);
        st4(dst, j << 2, X0, X1, X2, X3);
    }
    __syncthreads();
}

// inverse stage 6 (NS=1024): outputs are coalesced -> write gmem directly
__device__ __forceinline__ void fft_stage6_inv_g(const float2* __restrict__ src,
                                                 float* __restrict__ row0,
                                                 float* __restrict__ row1)
{
    const float inv = 0.015625f;        // 1/sqrt(4096)
#pragma unroll
    for (int q = 0; q < 4; q++) {
        int j = threadIdx.x + q * 256;  // 0..1023 ; k = j, base = j
        float2 a0 = src[SW(j)];
        float2 a1 = src[SW(j + 1024)];
        float2 a2 = src[SW(j + 2048)];
        float2 a3 = src[SW(j + 3072)];
        float2 w1 = g_tw[j];
        w1.y = -w1.y;                   // inverse
        float2 w2 = cmulf(w1, w1);
        float2 w3 = cmulf(w1, w2);
        a1 = cmulf(w1, a1);
        a2 = cmulf(w2, a2);
        a3 = cmulf(w3, a3);
        float2 X0, X1, X2, X3;
        r4bf<true>(a0, a1, a2, a3, X0, X1, X2, X3);
        row0[j       ] = tf32r(X0.x * inv);
        row1[j       ] = tf32r(X0.y * inv);
        row0[j + 1024] = tf32r(X1.x * inv);
        row1[j + 1024] = tf32r(X1.y * inv);
        row0[j + 2048] = tf32r(X2.x * inv);
        row1[j + 2048] = tf32r(X2.y * inv);
        row0[j + 3072] = tf32r(X3.x * inv);
        row1[j + 3072] = tf32r(X3.y * inv);
    }
}

__global__ __launch_bounds__(256) void fftmix_k(
    const float* __restrict__ rmat, const float* __restrict__ imat,
    const float* __restrict__ rb,   const float* __restrict__ ib)
{
    extern __shared__ float2 sb[];
    float2* b0 = sb;
    float2* b1 = sb + FFT_BUF;

    int blk = blockIdx.x;
    int b   = blk / (HID / 2);
    int hp  = blk % (HID / 2);
    int h0  = 2 * hp;
    int h1  = h0 + 1;
    float* row0 = g_ht + ((size_t)(b * HID + h0)) * NTOK;
    float* row1 = row0 + NTOK;

    // forward FFT: gmem -> b0, then 5 smem stages; Z ends in b1
    fft_stage1_g(row0, row1, b0);
    fft_stage<false, 4>(b0, b1);
    fft_stage<false, 16>(b1, b0);
    fft_stage<false, 64>(b0, b1);
    fft_stage<false, 256>(b1, b0);
    fft_stage<false, 1024>(b0, b1);

    PwParams P;
    P.ra0 = rmat[(size_t)h0 * HID + h0];
    P.ia0 = imat[(size_t)h0 * HID + h0];
    P.ra1 = rmat[(size_t)h1 * HID + h1];
    P.ia1 = imat[(size_t)h1 * HID + h1];
    P.rb0 = rb[h0]; P.ib0 = ib[h0];
    P.rb1 = rb[h1]; P.ib1 = ib[h1];

    // inverse FFT with pointwise fused into stage 1's read; final stage
    // writes gmem (scaled, tf32-rounded)
    inv_stage1_pw(b1, b0, P);
    fft_stage<true, 4>(b0, b1);
    fft_stage<true, 16>(b1, b0);
    fft_stage<true, 64>(b0, b1);
    fft_stage<true, 256>(b1, b0);
    fft_stage6_inv_g(b0, row0, row1);
}

// ---------------------------------------------------------------------------
// GEMM2 (tf32, cp.async 5-stage): y[b,n,c] = BN( sum_h ht[b,h,n] * W2[c,h] )
// ---------------------------------------------------------------------------
#define G2_ASZ (16 * 264)
#define G2_WSZ (64 * 20)
#define G2_SSZ (G2_ASZ + G2_WSZ)
#define G2_DEPTH 5
#define G2_SMEM (G2_DEPTH * G2_SSZ * 4)

__global__ __launch_bounds__(256, 2) void gemm2_k(
    const float* __restrict__ W2,
    const float* __restrict__ g2, const float* __restrict__ b2,
    const float* __restrict__ m2, const float* __restrict__ v2,
    float* __restrict__ y)
{
    extern __shared__ uint32_t smem_u[];

    int tid  = threadIdx.x;
    int lane = tid & 31;
    int wid  = tid >> 5;
    int wm   = wid >> 1;
    int wn   = wid & 1;
    int lk   = lane & 3;
    int lg   = lane >> 2;

    int n0 = blockIdx.x * 256;
    int c0 = blockIdx.y * 64;
    int b  = blockIdx.z;

    const float* hp = g_ht + (size_t)b * HID * NTOK + n0;
    const float* wp = W2 + (size_t)c0 * HID;

    uint32_t sbase = (uint32_t)__cvta_generic_to_shared(smem_u);

    int arow = tid >> 6;
    int aoff = (tid & 63) << 2;
    int wrow = tid >> 2;
    int woff = (tid & 3) << 2;

#define G2_LOAD(st, kc)                                                          \
    {                                                                            \
        uint32_t ao = sbase + (st) * G2_SSZ * 4;                                 \
        uint32_t wo = ao + G2_ASZ * 4;                                           \
        _Pragma("unroll")                                                        \
        for (int i = 0; i < 4; i++) {                                            \
            int row = arow + i * 4;                                              \
            cp_async16(ao + (row * 264 + aoff) * 4,                              \
                       hp + (size_t)((kc) * 16 + row) * NTOK + aoff);            \
        }                                                                        \
        cp_async16(wo + (wrow * 20 + woff) * 4,                                  \
                   wp + (size_t)wrow * HID + (kc) * 16 + woff);                  \
    }

    float4 acc[4][4];
#pragma unroll
    for (int i = 0; i < 4; i++)
#pragma unroll
        for (int j = 0; j < 4; j++) acc[i][j] = make_float4(0.f, 0.f, 0.f, 0.f);

    G2_LOAD(0, 0); CP_COMMIT();
    G2_LOAD(1, 1); CP_COMMIT();
    G2_LOAD(2, 2); CP_COMMIT();
    G2_LOAD(3, 3); CP_COMMIT();

    for (int kc = 0; kc < 48; kc++) {
        CP_WAIT3();
        __syncthreads();
        if (kc + 4 < 48) { G2_LOAD((kc + 4) % G2_DEPTH, kc + 4); }
        CP_COMMIT();

        const uint32_t* sA = smem_u + (kc % G2_DEPTH) * G2_SSZ;
        const uint32_t* sW = sA + G2_ASZ;
#pragma unroll
        for (int k0 = 0; k0 < 16; k0 += 8) {
            uint32_t afr[4][4], bfr[4][2];
#pragma unroll
            for (int mf = 0; mf < 4; mf++) {
                int mb = wm * 64 + mf * 16 + lg;
                afr[mf][0] = sA[(k0 + lk    ) * 264 + mb    ];
                afr[mf][1] = sA[(k0 + lk    ) * 264 + mb + 8];
                afr[mf][2] = sA[(k0 + lk + 4) * 264 + mb    ];
                afr[mf][3] = sA[(k0 + lk + 4) * 264 + mb + 8];
            }
#pragma unroll
            for (int nf = 0; nf < 4; nf++) {
                int cb = wn * 32 + nf * 8 + lg;
                bfr[nf][0] = sW[cb * 20 + k0 + lk    ];
                bfr[nf][1] = sW[cb * 20 + k0 + lk + 4];
            }
#pragma unroll
            for (int mf = 0; mf < 4; mf++)
#pragma unroll
                for (int nf = 0; nf < 4; nf++)
                    mma_tf32(acc[mf][nf], afr[mf], bfr[nf]);
        }
    }

    float scv[4][2], shv[4][2];
#pragma unroll
    for (int nf = 0; nf < 4; nf++) {
        int c = c0 + wn * 32 + nf * 8 + 2 * lk;
#pragma unroll
        for (int j = 0; j < 2; j++) {
            scv[nf][j] = g2[c + j] * rsqrtf(v2[c + j] + EPSBN);
            shv[nf][j] = b2[c + j] - m2[c + j] * scv[nf][j];
        }
    }
#pragma unroll
    for (int mf = 0; mf < 4; mf++) {
        int n_r0 = n0 + wm * 64 + mf * 16 + lg;
        int n_r1 = n_r0 + 8;
        float* p0 = y + ((size_t)(b * NTOK + n_r0)) * CIN;
        float* p1 = y + ((size_t)(b * NTOK + n_r1)) * CIN;
#pragma unroll
        for (int nf = 0; nf < 4; nf++) {
            int c = c0 + wn * 32 + nf * 8 + 2 * lk;
            float4 a = acc[mf][nf];
            float2 o0, o1;
            o0.x = fmaf(a.x, scv[nf][0], shv[nf][0]);
            o0.y = fmaf(a.y, scv[nf][1], shv[nf][1]);
            o1.x = fmaf(a.z, scv[nf][0], shv[nf][0]);
            o1.y = fmaf(a.w, scv[nf][1], shv[nf][1]);
            *(float2*)(p0 + c) = o0;
            *(float2*)(p1 + c) = o1;
        }
    }
}

// ---------------------------------------------------------------------------
extern "C" void kernel_launch(void* const* d_in, const int* in_sizes, int n_in,
                              void* d_out, int out_size)
{
    const float* x  = (const float*)d_in[0];
    const float* W1 = (const float*)d_in[1];
    const float* g1 = (const float*)d_in[2];
    const float* b1 = (const float*)d_in[3];
    const float* m1 = (const float*)d_in[4];
    const float* v1 = (const float*)d_in[5];
    const float* r  = (const float*)d_in[6];
    const float* im = (const float*)d_in[7];
    const float* rb = (const float*)d_in[8];
    const float* ib = (const float*)d_in[9];
    const float* W2 = (const float*)d_in[10];
    const float* g2 = (const float*)d_in[11];
    const float* b2 = (const float*)d_in[12];
    const float* m2 = (const float*)d_in[13];
    const float* v2 = (const float*)d_in[14];
    float* y = (float*)d_out;

    static bool attr_set = false;
    if (!attr_set) {
        cudaFuncSetAttribute(fftmix_k, cudaFuncAttributeMaxDynamicSharedMemorySize,
                             2 * FFT_BUF * sizeof(float2));
        cudaFuncSetAttribute(gemm1_k, cudaFuncAttributeMaxDynamicSharedMemorySize, G1_SMEM);
        cudaFuncSetAttribute(gemm2_k, cudaFuncAttributeMaxDynamicSharedMemorySize, G2_SMEM);
        attr_set = true;
    }

    twiddle_init_k<<<16, 256>>>();
    gemm1_k<<<dim3(NTOK / 128, HID / 128, BATCH), 256, G1_SMEM>>>(x, W1, g1, b1, m1, v1);
    fftmix_k<<<BATCH * (HID / 2), 256, 2 * FFT_BUF * sizeof(float2)>>>(r, im, rb, ib);
    gemm2_k<<<dim3(NTOK / 256, CIN / 64, BATCH), 256, G2_SMEM>>>(W2, g2, b2, m2, v2, y);
}